// round 13
// baseline (speedup 1.0000x reference)
#include <cuda_runtime.h>
#include <cstdint>

// ---------------------------------------------------------------------------
// Problem dims
// ---------------------------------------------------------------------------
#define BB 4
#define CC 64
#define HF 256
#define WF 256
#define H2 128
#define W2 128
#define NPIX  (BB*H2*W2)       // 65536 pixels per [B,128,128] tensor

// ---------------------------------------------------------------------------
// Scratch (one big __device__ array; allocation-free rule)
// ---------------------------------------------------------------------------
static const size_t OFF1 = 0;                       // [4,32,256,256]
static const size_t OFF2 = OFF1 + (size_t)4*32*256*256;  // [4,6,256,256]
static const size_t OFFP = OFF2 + (size_t)4*6*256*256;   // [4,6,128,128] tanh*0.25 pooled
static const size_t LLo  = OFFP + (size_t)4*6*128*128;
static const size_t LHo  = LLo + (size_t)4*64*128*128;
static const size_t HLo  = LHo + (size_t)4*64*128*128;
static const size_t HHo  = HLo + (size_t)4*64*128*128;
static const size_t ZLH  = HHo + (size_t)4*64*128*128;
static const size_t ZHL  = ZLH + (size_t)4*64*128*128;
static const size_t ZHH  = ZHL + (size_t)4*64*128*128;
static const size_t BC0  = ZHH + (size_t)4*64*128*128;   // conv NHWC outs, 4 contiguous bands
static const size_t BC1  = BC0 + (size_t)4*64*128*128;
static const size_t BC2  = BC1 + (size_t)4*64*128*128;
static const size_t BC3  = BC2 + (size_t)4*64*128*128;
static const size_t FZ   = BC3 + (size_t)4*64*128*128;   // fusion z NHWC
static const size_t SCRATCH_FLOATS = FZ + (size_t)4*64*128*128;

__device__ float g_scratch[SCRATCH_FLOATS];

__device__ __forceinline__ float gelu_f(float x) {
    return 0.5f * x * (1.0f + erff(x * 0.70710678118654752440f));
}

// ---------------------------------------------------------------------------
// Tiled 3x3 conv, pad=1.  Block (32,4)=128 thr. Output tile 32w x 16h,
// CO_CHUNK output channels per block-z slice, 4 rows per thread.
// ---------------------------------------------------------------------------
template<int CI, int CO_CHUNK, bool GELU, bool NHWC>
__global__ __launch_bounds__(128)
void conv3x3_kernel(const float* __restrict__ in, const float* __restrict__ w,
                    const float* __restrict__ bias, float* __restrict__ out,
                    int CO, int H, int W)
{
    __shared__ float s_in[18][34];
    __shared__ float s_w[CO_CHUNK * 9];

    const int tx = threadIdx.x, ty = threadIdx.y;
    const int tid = ty * 32 + tx;
    const int chunks = CO / CO_CHUNK;
    const int b = blockIdx.z / chunks;
    const int coBase = (blockIdx.z % chunks) * CO_CHUNK;
    const int x0 = blockIdx.x * 32;
    const int y0 = blockIdx.y * 16;

    float acc[CO_CHUNK][4];
#pragma unroll
    for (int c = 0; c < CO_CHUNK; c++)
#pragma unroll
        for (int r = 0; r < 4; r++) acc[c][r] = 0.f;

    const float* inb = in + (size_t)b * CI * H * W;

    for (int ci = 0; ci < CI; ci++) {
        const float* inc = inb + (size_t)ci * H * W;
        for (int idx = tid; idx < 18 * 34; idx += 128) {
            int row = idx / 34, col = idx % 34;
            int gy = y0 + row - 1, gx = x0 + col - 1;
            float v = 0.f;
            if (gy >= 0 && gy < H && gx >= 0 && gx < W) v = inc[(size_t)gy * W + gx];
            s_in[row][col] = v;
        }
        // FIX (R11): CO_CHUNK*9 can exceed blockDim (144 > 128) — must stride.
        for (int i = tid; i < CO_CHUNK * 9; i += 128)
            s_w[i] = w[((size_t)(coBase + i / 9) * CI + ci) * 9 + (i % 9)];
        __syncthreads();

        float v[6][3];
#pragma unroll
        for (int rr = 0; rr < 6; rr++)
#pragma unroll
            for (int cc = 0; cc < 3; cc++) v[rr][cc] = s_in[ty * 4 + rr][tx + cc];

#pragma unroll
        for (int c = 0; c < CO_CHUNK; c++) {
#pragma unroll
            for (int k = 0; k < 9; k++) {
                const float wv = s_w[c * 9 + k];
                const int ky = k / 3, kx = k % 3;
#pragma unroll
                for (int r = 0; r < 4; r++)
                    acc[c][r] += v[r + ky][kx] * wv;
            }
        }
        __syncthreads();
    }

    const int x = x0 + tx;
#pragma unroll
    for (int c = 0; c < CO_CHUNK; c++) {
        const float bv = bias[coBase + c];
#pragma unroll
        for (int r = 0; r < 4; r++) {
            const int y = y0 + ty * 4 + r;
            float val = acc[c][r] + bv;
            if (GELU) val = gelu_f(val);
            if (NHWC)
                out[(((size_t)b * H + y) * W + x) * CO + coBase + c] = val;
            else
                out[(((size_t)b * CO + coBase + c) * H + y) * W + x] = val;
        }
    }
}

// ---------------------------------------------------------------------------
// Haar DWT (stride-2). Matches ref ordering: xl/xh then second pass, *SQ2 each.
// ---------------------------------------------------------------------------
__global__ void dwt_kernel(const float* __restrict__ R, float* __restrict__ ll,
                           float* __restrict__ lh, float* __restrict__ hl,
                           float* __restrict__ hh)
{
    int idx = blockIdx.x * 256 + threadIdx.x;       // over B*C*128*128
    if (idx >= BB * CC * H2 * W2) return;
    int x = idx & 127;
    int y = (idx >> 7) & 127;
    int bc = idx >> 14;
    const float2* R2 = (const float2*)R;
    size_t r0 = ((size_t)bc * 256 + 2 * y) * 128 + x;
    float2 ab = R2[r0];
    float2 cd = R2[r0 + 128];
    const float S = 0.70710678118654752440f;
    float xl0 = (ab.x + ab.y) * S, xh0 = (ab.y - ab.x) * S;
    float xl1 = (cd.x + cd.y) * S, xh1 = (cd.y - cd.x) * S;
    ll[idx] = (xl0 + xl1) * S;
    lh[idx] = (xl1 - xl0) * S;
    hl[idx] = (xh0 + xh1) * S;
    hh[idx] = (xh1 - xh0) * S;
}

// ---------------------------------------------------------------------------
// 2x2 avg-pool of conv2 output, then tanh * 0.25 (deform displacement field)
// ---------------------------------------------------------------------------
__global__ void pool_tanh_kernel(const float* __restrict__ in, float* __restrict__ out)
{
    int idx = blockIdx.x * 256 + threadIdx.x;        // over 4*6*128*128
    if (idx >= BB * 6 * H2 * W2) return;
    int x = idx & 127;
    int y = (idx >> 7) & 127;
    int bc = idx >> 14;
    const float2* in2 = (const float2*)in;
    size_t r0 = ((size_t)bc * 256 + 2 * y) * 128 + x;
    float2 ab = in2[r0];
    float2 cd = in2[r0 + 128];
    float s = 0.25f * (((ab.x + ab.y) + cd.x) + cd.y);
    out[idx] = tanhf(s) * 0.25f;
}

// ---------------------------------------------------------------------------
// Bilinear grid-sample, padding=reflection, align_corners=True.
// ix = x + off_x*63.5 (identical to ref's normalized-coord math).
// One thread per (b,y,x), loops 64 channels. blockIdx.y = band.
// ---------------------------------------------------------------------------
__global__ void deform_kernel(const float* __restrict__ lh, const float* __restrict__ hl,
                              const float* __restrict__ hh, const float* __restrict__ offp,
                              float* __restrict__ zlh, float* __restrict__ zhl,
                              float* __restrict__ zhh)
{
    int pix = blockIdx.x * 256 + threadIdx.x;
    if (pix >= NPIX) return;
    int band = blockIdx.y;
    int x = pix & 127, y = (pix >> 7) & 127, b = pix >> 14;
    const float* in;
    float* out;
    if (band == 0)      { in = lh; out = zlh; }
    else if (band == 1) { in = hl; out = zhl; }
    else                { in = hh; out = zhh; }

    size_t obase = (((size_t)b * 6 + band * 2) * 128 + y) * 128 + x;
    float ox = offp[obase];
    float oy = offp[obase + 16384];
    float ix = (float)x + ox * 63.5f;
    float iy = (float)y + oy * 63.5f;
    float t;
    t = fabsf(ix); t = fmodf(t, 254.f); ix = (t > 127.f) ? (254.f - t) : t;
    t = fabsf(iy); t = fmodf(t, 254.f); iy = (t > 127.f) ? (254.f - t) : t;
    float xf = floorf(ix), yf = floorf(iy);
    float wx = ix - xf, wy = iy - yf;
    int ax0 = min(max((int)xf, 0), 127), ax1 = min(ax0 + 1, 127);
    int ay0 = min(max((int)yf, 0), 127), ay1 = min(ay0 + 1, 127);
    float w00 = (1.f - wx) * (1.f - wy);
    float w01 = wx * (1.f - wy);
    float w10 = (1.f - wx) * wy;
    float w11 = wx * wy;

    const float* inb = in + (size_t)b * 64 * 16384;
    float* outb = out + (size_t)b * 64 * 16384 + (size_t)y * 128 + x;
    int r0 = ay0 * 128, r1 = ay1 * 128;
#pragma unroll 4
    for (int c = 0; c < 64; c++) {
        const float* pc = inb + (size_t)c * 16384;
        float v = pc[r0 + ax0] * w00 + pc[r0 + ax1] * w01 +
                  pc[r1 + ax0] * w10 + pc[r1 + ax1] * w11;
        outb[(size_t)c * 16384] = v;
    }
}

// ---------------------------------------------------------------------------
// Fused LayerNorm + FFN(64->256 GELU ->64) + residual. NHWC input.
// One warp processes 4 pixels; weights staged in smem with conflict-free
// lane layouts (j = lane + 32t). mode nchw=1 writes NCHW (final output).
// ---------------------------------------------------------------------------
#define LN_SMEM_FLOATS (64*256 + 256*64 + 256 + 64 + 64 + 64 + 8*4*64 + 8*4*256)
#define LN_SMEM_BYTES  (LN_SMEM_FLOATS * 4)

__global__ __launch_bounds__(256)
void ln_ffn_kernel(const float* in, float* out,
                   const float* __restrict__ lnw, const float* __restrict__ lnb,
                   const float* __restrict__ Wfc1, const float* __restrict__ bfc1,
                   const float* __restrict__ Wfc2, const float* __restrict__ bfc2,
                   int npix, int nchw)
{
    extern __shared__ float sm[];
    float* sW1 = sm;                // [64][256]
    float* sW2 = sW1 + 64 * 256;    // [256][64]
    float* sb1 = sW2 + 256 * 64;    // 256
    float* sb2 = sb1 + 256;         // 64
    float* slw = sb2 + 64;          // 64
    float* slb = slw + 64;          // 64
    float* sZN = slb + 64;          // 8 warps * 4 px * 64
    float* sH  = sZN + 8 * 4 * 64;  // 8 warps * 4 px * 256

    const int tid = threadIdx.x;
    for (int i = tid; i < 64 * 256; i += 256) { sW1[i] = Wfc1[i]; sW2[i] = Wfc2[i]; }
    if (tid < 256) sb1[tid] = bfc1[tid];
    if (tid < 64) { sb2[tid] = bfc2[tid]; slw[tid] = lnw[tid]; slb[tid] = lnb[tid]; }
    __syncthreads();

    const int warp = tid >> 5, lane = tid & 31;
    float* zn = sZN + warp * 256;
    float* hb = sH + warp * 1024;
    const float lw0 = slw[lane], lw1 = slw[lane + 32];
    const float lb0 = slb[lane], lb1 = slb[lane + 32];
    const float bo0 = sb2[lane], bo1 = sb2[lane + 32];

    const int task0 = (blockIdx.x * 8 + warp) * 4;
    const int tstride = gridDim.x * 8 * 4;

    for (int base = task0; base < npix; base += tstride) {
        float za[4][2];
#pragma unroll
        for (int p = 0; p < 4; p++) {
            const int pix = base + p;
            float a0 = in[(size_t)pix * 64 + lane];
            float a1 = in[(size_t)pix * 64 + 32 + lane];
            float s = a0 + a1, sq = a0 * a0 + a1 * a1;
#pragma unroll
            for (int o = 16; o; o >>= 1) {
                s  += __shfl_xor_sync(0xffffffffu, s, o);
                sq += __shfl_xor_sync(0xffffffffu, sq, o);
            }
            float mu = s * 0.015625f;
            float var = sq * 0.015625f - mu * mu;
            float rs = rsqrtf(var + 1e-5f);
            zn[p * 64 + lane]      = (a0 - mu) * rs * lw0 + lb0;
            zn[p * 64 + lane + 32] = (a1 - mu) * rs * lw1 + lb1;
            za[p][0] = a0; za[p][1] = a1;
        }
        __syncwarp();

        float hacc[8][4];
#pragma unroll
        for (int t = 0; t < 8; t++) {
            float bv = sb1[lane + 32 * t];
#pragma unroll
            for (int p = 0; p < 4; p++) hacc[t][p] = bv;
        }
        for (int i = 0; i < 64; i++) {
            float z0 = zn[i], z1 = zn[64 + i], z2 = zn[128 + i], z3 = zn[192 + i];
#pragma unroll
            for (int t = 0; t < 8; t++) {
                float wv = sW1[i * 256 + lane + 32 * t];
                hacc[t][0] += z0 * wv;
                hacc[t][1] += z1 * wv;
                hacc[t][2] += z2 * wv;
                hacc[t][3] += z3 * wv;
            }
        }
#pragma unroll
        for (int t = 0; t < 8; t++)
#pragma unroll
            for (int p = 0; p < 4; p++)
                hb[p * 256 + lane + 32 * t] = gelu_f(hacc[t][p]);
        __syncwarp();

        float f0[4], f1[4];
#pragma unroll
        for (int p = 0; p < 4; p++) { f0[p] = bo0; f1[p] = bo1; }
        for (int j = 0; j < 256; j++) {
            float w0 = sW2[j * 64 + lane], w1 = sW2[j * 64 + lane + 32];
            float h0 = hb[j], h1 = hb[256 + j], h2 = hb[512 + j], h3 = hb[768 + j];
            f0[0] += h0 * w0; f1[0] += h0 * w1;
            f0[1] += h1 * w0; f1[1] += h1 * w1;
            f0[2] += h2 * w0; f1[2] += h2 * w1;
            f0[3] += h3 * w0; f1[3] += h3 * w1;
        }
#pragma unroll
        for (int p = 0; p < 4; p++) {
            const int pix = base + p;
            float o0 = za[p][0] + f0[p];
            float o1 = za[p][1] + f1[p];
            if (nchw) {
                int b = pix >> 14, y = (pix >> 7) & 127, x = pix & 127;
                out[(((size_t)b * 64 + lane) * 128 + y) * 128 + x] = o0;
                out[(((size_t)b * 64 + lane + 32) * 128 + y) * 128 + x] = o1;
            } else {
                out[(size_t)pix * 64 + lane] = o0;
                out[(size_t)pix * 64 + 32 + lane] = o1;
            }
        }
        __syncwarp();
    }
}

// ---------------------------------------------------------------------------
// 1x1 fusion conv: z[64] = fus_w[64][256] @ concat(f_ll,f_lh,f_hl,f_hh) + b.
// Weights staged transposed ([k][co]) for conflict-free lane access.
// ---------------------------------------------------------------------------
#define FUSE_SMEM_FLOATS (256*64 + 64 + 8*4*256)
#define FUSE_SMEM_BYTES  (FUSE_SMEM_FLOATS * 4)

__global__ __launch_bounds__(256)
void fuse_kernel(const float* __restrict__ in0, const float* __restrict__ in1,
                 const float* __restrict__ in2, const float* __restrict__ in3,
                 const float* __restrict__ fw, const float* __restrict__ fb,
                 float* __restrict__ out, int npix)
{
    extern __shared__ float sm[];
    float* sFw = sm;               // [256][64] (k-major, transposed)
    float* sfb = sFw + 16384;      // 64
    float* sV  = sfb + 64;         // 8 warps * 4 px * 256

    const int tid = threadIdx.x;
    for (int i = tid; i < 16384; i += 256) {
        int co = i >> 8, k = i & 255;
        sFw[k * 64 + co] = fw[i];
    }
    if (tid < 64) sfb[tid] = fb[tid];
    __syncthreads();

    const int warp = tid >> 5, lane = tid & 31;
    float* v = sV + warp * 1024;
    const float bo0 = sfb[lane], bo1 = sfb[lane + 32];
    const int task0 = (blockIdx.x * 8 + warp) * 4;
    const int tstride = gridDim.x * 8 * 4;

    for (int base = task0; base < npix; base += tstride) {
#pragma unroll
        for (int p = 0; p < 4; p++) {
            size_t off = (size_t)(base + p) * 64;
            v[p * 256 + 0 * 64 + lane] = in0[off + lane];
            v[p * 256 + 0 * 64 + lane + 32] = in0[off + lane + 32];
            v[p * 256 + 1 * 64 + lane] = in1[off + lane];
            v[p * 256 + 1 * 64 + lane + 32] = in1[off + lane + 32];
            v[p * 256 + 2 * 64 + lane] = in2[off + lane];
            v[p * 256 + 2 * 64 + lane + 32] = in2[off + lane + 32];
            v[p * 256 + 3 * 64 + lane] = in3[off + lane];
            v[p * 256 + 3 * 64 + lane + 32] = in3[off + lane + 32];
        }
        __syncwarp();
        float z0[4], z1[4];
#pragma unroll
        for (int p = 0; p < 4; p++) { z0[p] = bo0; z1[p] = bo1; }
        for (int k = 0; k < 256; k++) {
            float w0 = sFw[k * 64 + lane], w1 = sFw[k * 64 + lane + 32];
            float v0 = v[k], v1 = v[256 + k], v2 = v[512 + k], v3 = v[768 + k];
            z0[0] += v0 * w0; z1[0] += v0 * w1;
            z0[1] += v1 * w0; z1[1] += v1 * w1;
            z0[2] += v2 * w0; z1[2] += v2 * w1;
            z0[3] += v3 * w0; z1[3] += v3 * w1;
        }
#pragma unroll
        for (int p = 0; p < 4; p++) {
            out[(size_t)(base + p) * 64 + lane] = z0[p];
            out[(size_t)(base + p) * 64 + 32 + lane] = z1[p];
        }
        __syncwarp();
    }
}

// ---------------------------------------------------------------------------
// Launch
// ---------------------------------------------------------------------------
extern "C" void kernel_launch(void* const* d_in, const int* in_sizes, int n_in,
                              void* d_out, int out_size)
{
    const float* R      = (const float*)d_in[0];
    const float* off_w1 = (const float*)d_in[1];
    const float* off_b1 = (const float*)d_in[2];
    const float* off_w2 = (const float*)d_in[3];
    const float* off_b2 = (const float*)d_in[4];
    const float* w_ll   = (const float*)d_in[5];
    const float* b_ll   = (const float*)d_in[6];
    const float* w_lh   = (const float*)d_in[7];
    const float* b_lh   = (const float*)d_in[8];
    const float* w_hl   = (const float*)d_in[9];
    const float* b_hl   = (const float*)d_in[10];
    const float* w_hh   = (const float*)d_in[11];
    const float* b_hh   = (const float*)d_in[12];
    const float* ln_w   = (const float*)d_in[13];
    const float* ln_b   = (const float*)d_in[14];
    const float* ffn_w1 = (const float*)d_in[15];
    const float* ffn_b1 = (const float*)d_in[16];
    const float* ffn_w2 = (const float*)d_in[17];
    const float* ffn_b2 = (const float*)d_in[18];
    const float* fus_w  = (const float*)d_in[19];
    const float* fus_b  = (const float*)d_in[20];
    float* out = (float*)d_out;

    float* S = nullptr;
    cudaGetSymbolAddress((void**)&S, g_scratch);

    float* off1 = S + OFF1;
    float* off2 = S + OFF2;
    float* offp = S + OFFP;
    float* pll = S + LLo;
    float* plh = S + LHo;
    float* phl = S + HLo;
    float* phh = S + HHo;
    float* zlh = S + ZLH;
    float* zhl = S + ZHL;
    float* zhh = S + ZHH;
    float* bc0 = S + BC0;
    float* bc1 = S + BC1;
    float* bc2 = S + BC2;
    float* bc3 = S + BC3;
    float* fz  = S + FZ;

    cudaFuncSetAttribute((const void*)ln_ffn_kernel,
                         cudaFuncAttributeMaxDynamicSharedMemorySize, LN_SMEM_BYTES);
    cudaFuncSetAttribute((const void*)fuse_kernel,
                         cudaFuncAttributeMaxDynamicSharedMemorySize, FUSE_SMEM_BYTES);

    dim3 cblk(32, 4);

    // Offset network
    conv3x3_kernel<64, 16, true,  false><<<dim3(8, 16, 8), cblk>>>(R, off_w1, off_b1, off1, 32, HF, WF);
    conv3x3_kernel<32, 6,  false, false><<<dim3(8, 16, 4), cblk>>>(off1, off_w2, off_b2, off2, 6, HF, WF);
    pool_tanh_kernel<<<(BB * 6 * H2 * W2 + 255) / 256, 256>>>(off2, offp);

    // DWT + deform
    dwt_kernel<<<(BB * CC * H2 * W2 + 255) / 256, 256>>>(R, pll, plh, phl, phh);
    deform_kernel<<<dim3(NPIX / 256, 3), 256>>>(plh, phl, phh, offp, zlh, zhl, zhh);

    // Per-band conv3x3 (NHWC out)
    conv3x3_kernel<64, 16, false, true><<<dim3(4, 8, 16), cblk>>>(pll, w_ll, b_ll, bc0, 64, H2, W2);
    conv3x3_kernel<64, 16, false, true><<<dim3(4, 8, 16), cblk>>>(zlh, w_lh, b_lh, bc1, 64, H2, W2);
    conv3x3_kernel<64, 16, false, true><<<dim3(4, 8, 16), cblk>>>(zhl, w_hl, b_hl, bc2, 64, H2, W2);
    conv3x3_kernel<64, 16, false, true><<<dim3(4, 8, 16), cblk>>>(zhh, w_hh, b_hh, bc3, 64, H2, W2);

    // LN+FFN residual over all 4 bands at once (contiguous NHWC, in-place)
    ln_ffn_kernel<<<148, 256, LN_SMEM_BYTES>>>(bc0, bc0, ln_w, ln_b,
                                               ffn_w1, ffn_b1, ffn_w2, ffn_b2,
                                               4 * NPIX, 0);

    // 1x1 fusion conv
    fuse_kernel<<<148, 256, FUSE_SMEM_BYTES>>>(bc0, bc1, bc2, bc3, fus_w, fus_b, fz, NPIX);

    // Final LN+FFN residual, NCHW output
    ln_ffn_kernel<<<148, 256, LN_SMEM_BYTES>>>(fz, out, ln_w, ln_b,
                                               ffn_w1, ffn_b1, ffn_w2, ffn_b2,
                                               NPIX, 1);
}

// round 14
// speedup vs baseline: 1.0079x; 1.0079x over previous
#include <cuda_runtime.h>
#include <cstdint>

// ---------------------------------------------------------------------------
// Problem dims
// ---------------------------------------------------------------------------
#define BB 4
#define CC 64
#define HF 256
#define WF 256
#define H2 128
#define W2 128
#define NPIX  (BB*H2*W2)       // 65536 pixels per [B,128,128] tensor

// ---------------------------------------------------------------------------
// Scratch (one big __device__ array; allocation-free rule)
// ---------------------------------------------------------------------------
static const size_t OFF1 = 0;                       // [4,32,256,256]
static const size_t OFF2 = OFF1 + (size_t)4*32*256*256;  // [4,6,256,256]
static const size_t OFFP = OFF2 + (size_t)4*6*256*256;   // [4,6,128,128] tanh*0.25 pooled
static const size_t LLo  = OFFP + (size_t)4*6*128*128;
static const size_t LHo  = LLo + (size_t)4*64*128*128;
static const size_t HLo  = LHo + (size_t)4*64*128*128;
static const size_t HHo  = HLo + (size_t)4*64*128*128;
static const size_t ZLH  = HHo + (size_t)4*64*128*128;
static const size_t ZHL  = ZLH + (size_t)4*64*128*128;
static const size_t ZHH  = ZHL + (size_t)4*64*128*128;
static const size_t BC0  = ZHH + (size_t)4*64*128*128;   // conv NHWC outs, 4 contiguous bands
static const size_t BC1  = BC0 + (size_t)4*64*128*128;
static const size_t BC2  = BC1 + (size_t)4*64*128*128;
static const size_t BC3  = BC2 + (size_t)4*64*128*128;
static const size_t FZ   = BC3 + (size_t)4*64*128*128;   // fusion z NHWC
static const size_t SCRATCH_FLOATS = FZ + (size_t)4*64*128*128;

__device__ float g_scratch[SCRATCH_FLOATS];

__device__ __forceinline__ float gelu_f(float x) {
    return 0.5f * x * (1.0f + erff(x * 0.70710678118654752440f));
}

// ---------------------------------------------------------------------------
// Tiled 3x3 conv, pad=1.  Block (32,4)=128 thr. Output tile 32w x 16h,
// CO_CHUNK output channels per block-z slice, 4 rows per thread.
// ---------------------------------------------------------------------------
template<int CI, int CO_CHUNK, bool GELU, bool NHWC>
__global__ __launch_bounds__(128)
void conv3x3_kernel(const float* __restrict__ in, const float* __restrict__ w,
                    const float* __restrict__ bias, float* __restrict__ out,
                    int CO, int H, int W)
{
    __shared__ float s_in[18][34];
    __shared__ float s_w[CO_CHUNK * 9];

    const int tx = threadIdx.x, ty = threadIdx.y;
    const int tid = ty * 32 + tx;
    const int chunks = CO / CO_CHUNK;
    const int b = blockIdx.z / chunks;
    const int coBase = (blockIdx.z % chunks) * CO_CHUNK;
    const int x0 = blockIdx.x * 32;
    const int y0 = blockIdx.y * 16;

    float acc[CO_CHUNK][4];
#pragma unroll
    for (int c = 0; c < CO_CHUNK; c++)
#pragma unroll
        for (int r = 0; r < 4; r++) acc[c][r] = 0.f;

    const float* inb = in + (size_t)b * CI * H * W;

    for (int ci = 0; ci < CI; ci++) {
        const float* inc = inb + (size_t)ci * H * W;
        for (int idx = tid; idx < 18 * 34; idx += 128) {
            int row = idx / 34, col = idx % 34;
            int gy = y0 + row - 1, gx = x0 + col - 1;
            float v = 0.f;
            if (gy >= 0 && gy < H && gx >= 0 && gx < W) v = inc[(size_t)gy * W + gx];
            s_in[row][col] = v;
        }
        // FIX (R11): CO_CHUNK*9 can exceed blockDim (144 > 128) — must stride.
        for (int i = tid; i < CO_CHUNK * 9; i += 128)
            s_w[i] = w[((size_t)(coBase + i / 9) * CI + ci) * 9 + (i % 9)];
        __syncthreads();

        float v[6][3];
#pragma unroll
        for (int rr = 0; rr < 6; rr++)
#pragma unroll
            for (int cc = 0; cc < 3; cc++) v[rr][cc] = s_in[ty * 4 + rr][tx + cc];

#pragma unroll
        for (int c = 0; c < CO_CHUNK; c++) {
#pragma unroll
            for (int k = 0; k < 9; k++) {
                const float wv = s_w[c * 9 + k];
                const int ky = k / 3, kx = k % 3;
#pragma unroll
                for (int r = 0; r < 4; r++)
                    acc[c][r] += v[r + ky][kx] * wv;
            }
        }
        __syncthreads();
    }

    const int x = x0 + tx;
#pragma unroll
    for (int c = 0; c < CO_CHUNK; c++) {
        const float bv = bias[coBase + c];
#pragma unroll
        for (int r = 0; r < 4; r++) {
            const int y = y0 + ty * 4 + r;
            float val = acc[c][r] + bv;
            if (GELU) val = gelu_f(val);
            if (NHWC)
                out[(((size_t)b * H + y) * W + x) * CO + coBase + c] = val;
            else
                out[(((size_t)b * CO + coBase + c) * H + y) * W + x] = val;
        }
    }
}

// ---------------------------------------------------------------------------
// Haar DWT (stride-2). Matches ref ordering: xl/xh then second pass, *SQ2 each.
// ---------------------------------------------------------------------------
__global__ void dwt_kernel(const float* __restrict__ R, float* __restrict__ ll,
                           float* __restrict__ lh, float* __restrict__ hl,
                           float* __restrict__ hh)
{
    int idx = blockIdx.x * 256 + threadIdx.x;       // over B*C*128*128
    if (idx >= BB * CC * H2 * W2) return;
    int x = idx & 127;
    int y = (idx >> 7) & 127;
    int bc = idx >> 14;
    const float2* R2 = (const float2*)R;
    size_t r0 = ((size_t)bc * 256 + 2 * y) * 128 + x;
    float2 ab = R2[r0];
    float2 cd = R2[r0 + 128];
    const float S = 0.70710678118654752440f;
    float xl0 = (ab.x + ab.y) * S, xh0 = (ab.y - ab.x) * S;
    float xl1 = (cd.x + cd.y) * S, xh1 = (cd.y - cd.x) * S;
    ll[idx] = (xl0 + xl1) * S;
    lh[idx] = (xl1 - xl0) * S;
    hl[idx] = (xh0 + xh1) * S;
    hh[idx] = (xh1 - xh0) * S;
}

// ---------------------------------------------------------------------------
// 2x2 avg-pool of conv2 output, then tanh * 0.25 (deform displacement field)
// ---------------------------------------------------------------------------
__global__ void pool_tanh_kernel(const float* __restrict__ in, float* __restrict__ out)
{
    int idx = blockIdx.x * 256 + threadIdx.x;        // over 4*6*128*128
    if (idx >= BB * 6 * H2 * W2) return;
    int x = idx & 127;
    int y = (idx >> 7) & 127;
    int bc = idx >> 14;
    const float2* in2 = (const float2*)in;
    size_t r0 = ((size_t)bc * 256 + 2 * y) * 128 + x;
    float2 ab = in2[r0];
    float2 cd = in2[r0 + 128];
    float s = 0.25f * (((ab.x + ab.y) + cd.x) + cd.y);
    out[idx] = tanhf(s) * 0.25f;
}

// ---------------------------------------------------------------------------
// Bilinear grid-sample, padding=reflection, align_corners=True.
// ix = x + off_x*63.5 (identical to ref's normalized-coord math).
// One thread per (b,y,x), loops 64 channels. blockIdx.y = band.
// ---------------------------------------------------------------------------
__global__ void deform_kernel(const float* __restrict__ lh, const float* __restrict__ hl,
                              const float* __restrict__ hh, const float* __restrict__ offp,
                              float* __restrict__ zlh, float* __restrict__ zhl,
                              float* __restrict__ zhh)
{
    int pix = blockIdx.x * 256 + threadIdx.x;
    if (pix >= NPIX) return;
    int band = blockIdx.y;
    int x = pix & 127, y = (pix >> 7) & 127, b = pix >> 14;
    const float* in;
    float* out;
    if (band == 0)      { in = lh; out = zlh; }
    else if (band == 1) { in = hl; out = zhl; }
    else                { in = hh; out = zhh; }

    size_t obase = (((size_t)b * 6 + band * 2) * 128 + y) * 128 + x;
    float ox = offp[obase];
    float oy = offp[obase + 16384];
    float ix = (float)x + ox * 63.5f;
    float iy = (float)y + oy * 63.5f;
    float t;
    t = fabsf(ix); t = fmodf(t, 254.f); ix = (t > 127.f) ? (254.f - t) : t;
    t = fabsf(iy); t = fmodf(t, 254.f); iy = (t > 127.f) ? (254.f - t) : t;
    float xf = floorf(ix), yf = floorf(iy);
    float wx = ix - xf, wy = iy - yf;
    int ax0 = min(max((int)xf, 0), 127), ax1 = min(ax0 + 1, 127);
    int ay0 = min(max((int)yf, 0), 127), ay1 = min(ay0 + 1, 127);
    float w00 = (1.f - wx) * (1.f - wy);
    float w01 = wx * (1.f - wy);
    float w10 = (1.f - wx) * wy;
    float w11 = wx * wy;

    const float* inb = in + (size_t)b * 64 * 16384;
    float* outb = out + (size_t)b * 64 * 16384 + (size_t)y * 128 + x;
    int r0 = ay0 * 128, r1 = ay1 * 128;
#pragma unroll 4
    for (int c = 0; c < 64; c++) {
        const float* pc = inb + (size_t)c * 16384;
        float v = pc[r0 + ax0] * w00 + pc[r0 + ax1] * w01 +
                  pc[r1 + ax0] * w10 + pc[r1 + ax1] * w11;
        outb[(size_t)c * 16384] = v;
    }
}

// ---------------------------------------------------------------------------
// Fused LayerNorm + FFN(64->256 GELU ->64) + residual. NHWC input.
// One warp processes 4 pixels; weights staged in smem with conflict-free
// lane layouts (j = lane + 32t). mode nchw=1 writes NCHW (final output).
// ---------------------------------------------------------------------------
#define LN_SMEM_FLOATS (64*256 + 256*64 + 256 + 64 + 64 + 64 + 8*4*64 + 8*4*256)
#define LN_SMEM_BYTES  (LN_SMEM_FLOATS * 4)

__global__ __launch_bounds__(256)
void ln_ffn_kernel(const float* in, float* out,
                   const float* __restrict__ lnw, const float* __restrict__ lnb,
                   const float* __restrict__ Wfc1, const float* __restrict__ bfc1,
                   const float* __restrict__ Wfc2, const float* __restrict__ bfc2,
                   int npix, int nchw)
{
    extern __shared__ float sm[];
    float* sW1 = sm;                // [64][256]
    float* sW2 = sW1 + 64 * 256;    // [256][64]
    float* sb1 = sW2 + 256 * 64;    // 256
    float* sb2 = sb1 + 256;         // 64
    float* slw = sb2 + 64;          // 64
    float* slb = slw + 64;          // 64
    float* sZN = slb + 64;          // 8 warps * 4 px * 64
    float* sH  = sZN + 8 * 4 * 64;  // 8 warps * 4 px * 256

    const int tid = threadIdx.x;
    for (int i = tid; i < 64 * 256; i += 256) { sW1[i] = Wfc1[i]; sW2[i] = Wfc2[i]; }
    if (tid < 256) sb1[tid] = bfc1[tid];
    if (tid < 64) { sb2[tid] = bfc2[tid]; slw[tid] = lnw[tid]; slb[tid] = lnb[tid]; }
    __syncthreads();

    const int warp = tid >> 5, lane = tid & 31;
    float* zn = sZN + warp * 256;
    float* hb = sH + warp * 1024;
    const float lw0 = slw[lane], lw1 = slw[lane + 32];
    const float lb0 = slb[lane], lb1 = slb[lane + 32];
    const float bo0 = sb2[lane], bo1 = sb2[lane + 32];

    const int task0 = (blockIdx.x * 8 + warp) * 4;
    const int tstride = gridDim.x * 8 * 4;

    for (int base = task0; base < npix; base += tstride) {
        float za[4][2];
#pragma unroll
        for (int p = 0; p < 4; p++) {
            const int pix = base + p;
            float a0 = in[(size_t)pix * 64 + lane];
            float a1 = in[(size_t)pix * 64 + 32 + lane];
            float s = a0 + a1, sq = a0 * a0 + a1 * a1;
#pragma unroll
            for (int o = 16; o; o >>= 1) {
                s  += __shfl_xor_sync(0xffffffffu, s, o);
                sq += __shfl_xor_sync(0xffffffffu, sq, o);
            }
            float mu = s * 0.015625f;
            float var = sq * 0.015625f - mu * mu;
            float rs = rsqrtf(var + 1e-5f);
            zn[p * 64 + lane]      = (a0 - mu) * rs * lw0 + lb0;
            zn[p * 64 + lane + 32] = (a1 - mu) * rs * lw1 + lb1;
            za[p][0] = a0; za[p][1] = a1;
        }
        __syncwarp();

        float hacc[8][4];
#pragma unroll
        for (int t = 0; t < 8; t++) {
            float bv = sb1[lane + 32 * t];
#pragma unroll
            for (int p = 0; p < 4; p++) hacc[t][p] = bv;
        }
        for (int i = 0; i < 64; i++) {
            float z0 = zn[i], z1 = zn[64 + i], z2 = zn[128 + i], z3 = zn[192 + i];
#pragma unroll
            for (int t = 0; t < 8; t++) {
                float wv = sW1[i * 256 + lane + 32 * t];
                hacc[t][0] += z0 * wv;
                hacc[t][1] += z1 * wv;
                hacc[t][2] += z2 * wv;
                hacc[t][3] += z3 * wv;
            }
        }
#pragma unroll
        for (int t = 0; t < 8; t++)
#pragma unroll
            for (int p = 0; p < 4; p++)
                hb[p * 256 + lane + 32 * t] = gelu_f(hacc[t][p]);
        __syncwarp();

        float f0[4], f1[4];
#pragma unroll
        for (int p = 0; p < 4; p++) { f0[p] = bo0; f1[p] = bo1; }
        for (int j = 0; j < 256; j++) {
            float w0 = sW2[j * 64 + lane], w1 = sW2[j * 64 + lane + 32];
            float h0 = hb[j], h1 = hb[256 + j], h2 = hb[512 + j], h3 = hb[768 + j];
            f0[0] += h0 * w0; f1[0] += h0 * w1;
            f0[1] += h1 * w0; f1[1] += h1 * w1;
            f0[2] += h2 * w0; f1[2] += h2 * w1;
            f0[3] += h3 * w0; f1[3] += h3 * w1;
        }
#pragma unroll
        for (int p = 0; p < 4; p++) {
            const int pix = base + p;
            float o0 = za[p][0] + f0[p];
            float o1 = za[p][1] + f1[p];
            if (nchw) {
                int b = pix >> 14, y = (pix >> 7) & 127, x = pix & 127;
                out[(((size_t)b * 64 + lane) * 128 + y) * 128 + x] = o0;
                out[(((size_t)b * 64 + lane + 32) * 128 + y) * 128 + x] = o1;
            } else {
                out[(size_t)pix * 64 + lane] = o0;
                out[(size_t)pix * 64 + 32 + lane] = o1;
            }
        }
        __syncwarp();
    }
}

// ---------------------------------------------------------------------------
// 1x1 fusion conv: z[64] = fus_w[64][256] @ concat(f_ll,f_lh,f_hl,f_hh) + b.
// Weights staged transposed ([k][co]) for conflict-free lane access.
// ---------------------------------------------------------------------------
#define FUSE_SMEM_FLOATS (256*64 + 64 + 8*4*256)
#define FUSE_SMEM_BYTES  (FUSE_SMEM_FLOATS * 4)

__global__ __launch_bounds__(256)
void fuse_kernel(const float* __restrict__ in0, const float* __restrict__ in1,
                 const float* __restrict__ in2, const float* __restrict__ in3,
                 const float* __restrict__ fw, const float* __restrict__ fb,
                 float* __restrict__ out, int npix)
{
    extern __shared__ float sm[];
    float* sFw = sm;               // [256][64] (k-major, transposed)
    float* sfb = sFw + 16384;      // 64
    float* sV  = sfb + 64;         // 8 warps * 4 px * 256

    const int tid = threadIdx.x;
    for (int i = tid; i < 16384; i += 256) {
        int co = i >> 8, k = i & 255;
        sFw[k * 64 + co] = fw[i];
    }
    if (tid < 64) sfb[tid] = fb[tid];
    __syncthreads();

    const int warp = tid >> 5, lane = tid & 31;
    float* v = sV + warp * 1024;
    const float bo0 = sfb[lane], bo1 = sfb[lane + 32];
    const int task0 = (blockIdx.x * 8 + warp) * 4;
    const int tstride = gridDim.x * 8 * 4;

    for (int base = task0; base < npix; base += tstride) {
#pragma unroll
        for (int p = 0; p < 4; p++) {
            size_t off = (size_t)(base + p) * 64;
            v[p * 256 + 0 * 64 + lane] = in0[off + lane];
            v[p * 256 + 0 * 64 + lane + 32] = in0[off + lane + 32];
            v[p * 256 + 1 * 64 + lane] = in1[off + lane];
            v[p * 256 + 1 * 64 + lane + 32] = in1[off + lane + 32];
            v[p * 256 + 2 * 64 + lane] = in2[off + lane];
            v[p * 256 + 2 * 64 + lane + 32] = in2[off + lane + 32];
            v[p * 256 + 3 * 64 + lane] = in3[off + lane];
            v[p * 256 + 3 * 64 + lane + 32] = in3[off + lane + 32];
        }
        __syncwarp();
        float z0[4], z1[4];
#pragma unroll
        for (int p = 0; p < 4; p++) { z0[p] = bo0; z1[p] = bo1; }
        for (int k = 0; k < 256; k++) {
            float w0 = sFw[k * 64 + lane], w1 = sFw[k * 64 + lane + 32];
            float v0 = v[k], v1 = v[256 + k], v2 = v[512 + k], v3 = v[768 + k];
            z0[0] += v0 * w0; z1[0] += v0 * w1;
            z0[1] += v1 * w0; z1[1] += v1 * w1;
            z0[2] += v2 * w0; z1[2] += v2 * w1;
            z0[3] += v3 * w0; z1[3] += v3 * w1;
        }
#pragma unroll
        for (int p = 0; p < 4; p++) {
            out[(size_t)(base + p) * 64 + lane] = z0[p];
            out[(size_t)(base + p) * 64 + 32 + lane] = z1[p];
        }
        __syncwarp();
    }
}

// ---------------------------------------------------------------------------
// Launch
// ---------------------------------------------------------------------------
extern "C" void kernel_launch(void* const* d_in, const int* in_sizes, int n_in,
                              void* d_out, int out_size)
{
    const float* R      = (const float*)d_in[0];
    const float* off_w1 = (const float*)d_in[1];
    const float* off_b1 = (const float*)d_in[2];
    const float* off_w2 = (const float*)d_in[3];
    const float* off_b2 = (const float*)d_in[4];
    const float* w_ll   = (const float*)d_in[5];
    const float* b_ll   = (const float*)d_in[6];
    const float* w_lh   = (const float*)d_in[7];
    const float* b_lh   = (const float*)d_in[8];
    const float* w_hl   = (const float*)d_in[9];
    const float* b_hl   = (const float*)d_in[10];
    const float* w_hh   = (const float*)d_in[11];
    const float* b_hh   = (const float*)d_in[12];
    const float* ln_w   = (const float*)d_in[13];
    const float* ln_b   = (const float*)d_in[14];
    const float* ffn_w1 = (const float*)d_in[15];
    const float* ffn_b1 = (const float*)d_in[16];
    const float* ffn_w2 = (const float*)d_in[17];
    const float* ffn_b2 = (const float*)d_in[18];
    const float* fus_w  = (const float*)d_in[19];
    const float* fus_b  = (const float*)d_in[20];
    float* out = (float*)d_out;

    float* S = nullptr;
    cudaGetSymbolAddress((void**)&S, g_scratch);

    float* off1 = S + OFF1;
    float* off2 = S + OFF2;
    float* offp = S + OFFP;
    float* pll = S + LLo;
    float* plh = S + LHo;
    float* phl = S + HLo;
    float* phh = S + HHo;
    float* zlh = S + ZLH;
    float* zhl = S + ZHL;
    float* zhh = S + ZHH;
    float* bc0 = S + BC0;
    float* bc1 = S + BC1;
    float* bc2 = S + BC2;
    float* bc3 = S + BC3;
    float* fz  = S + FZ;

    cudaFuncSetAttribute((const void*)ln_ffn_kernel,
                         cudaFuncAttributeMaxDynamicSharedMemorySize, LN_SMEM_BYTES);
    cudaFuncSetAttribute((const void*)fuse_kernel,
                         cudaFuncAttributeMaxDynamicSharedMemorySize, FUSE_SMEM_BYTES);

    dim3 cblk(32, 4);

    // Offset network
    conv3x3_kernel<64, 16, true,  false><<<dim3(8, 16, 8), cblk>>>(R, off_w1, off_b1, off1, 32, HF, WF);
    conv3x3_kernel<32, 6,  false, false><<<dim3(8, 16, 4), cblk>>>(off1, off_w2, off_b2, off2, 6, HF, WF);
    pool_tanh_kernel<<<(BB * 6 * H2 * W2 + 255) / 256, 256>>>(off2, offp);

    // DWT + deform
    dwt_kernel<<<(BB * CC * H2 * W2 + 255) / 256, 256>>>(R, pll, plh, phl, phh);
    deform_kernel<<<dim3(NPIX / 256, 3), 256>>>(plh, phl, phh, offp, zlh, zhl, zhh);

    // Per-band conv3x3 (NHWC out)
    conv3x3_kernel<64, 16, false, true><<<dim3(4, 8, 16), cblk>>>(pll, w_ll, b_ll, bc0, 64, H2, W2);
    conv3x3_kernel<64, 16, false, true><<<dim3(4, 8, 16), cblk>>>(zlh, w_lh, b_lh, bc1, 64, H2, W2);
    conv3x3_kernel<64, 16, false, true><<<dim3(4, 8, 16), cblk>>>(zhl, w_hl, b_hl, bc2, 64, H2, W2);
    conv3x3_kernel<64, 16, false, true><<<dim3(4, 8, 16), cblk>>>(zhh, w_hh, b_hh, bc3, 64, H2, W2);

    // LN+FFN residual over all 4 bands at once (contiguous NHWC, in-place)
    ln_ffn_kernel<<<148, 256, LN_SMEM_BYTES>>>(bc0, bc0, ln_w, ln_b,
                                               ffn_w1, ffn_b1, ffn_w2, ffn_b2,
                                               4 * NPIX, 0);

    // 1x1 fusion conv
    fuse_kernel<<<148, 256, FUSE_SMEM_BYTES>>>(bc0, bc1, bc2, bc3, fus_w, fus_b, fz, NPIX);

    // Final LN+FFN residual, NCHW output
    ln_ffn_kernel<<<148, 256, LN_SMEM_BYTES>>>(fz, out, ln_w, ln_b,
                                               ffn_w1, ffn_b1, ffn_w2, ffn_b2,
                                               NPIX, 1);
}

// round 15
// speedup vs baseline: 1.1865x; 1.1772x over previous
#include <cuda_runtime.h>
#include <cstdint>

// ---------------------------------------------------------------------------
// Problem dims
// ---------------------------------------------------------------------------
#define BB 4
#define CC 64
#define HF 256
#define WF 256
#define H2 128
#define W2 128
#define NPIX  (BB*H2*W2)       // 65536 pixels per [B,128,128] tensor
#define BANDSZ ((size_t)BB*64*H2*W2)

// ---------------------------------------------------------------------------
// Scratch (one big __device__ array; allocation-free rule)
// ---------------------------------------------------------------------------
static const size_t OFF1 = 0;                       // [4,32,256,256]
static const size_t OFF2 = OFF1 + (size_t)4*32*256*256;  // [4,6,256,256]
static const size_t OFFP = OFF2 + (size_t)4*6*256*256;   // [4,6,128,128] tanh*0.25 pooled
static const size_t LLo  = OFFP + (size_t)4*6*128*128;
static const size_t LHo  = LLo + BANDSZ;
static const size_t HLo  = LHo + BANDSZ;
static const size_t HHo  = HLo + BANDSZ;
static const size_t ZLH  = HHo + BANDSZ;
static const size_t ZHL  = ZLH + BANDSZ;
static const size_t ZHH  = ZHL + BANDSZ;
static const size_t BC0  = ZHH + BANDSZ;   // conv NHWC outs, 4 contiguous bands
static const size_t FZ   = BC0 + 4*BANDSZ; // fusion z NHWC
static const size_t SCRATCH_FLOATS = FZ + BANDSZ;

__device__ float g_scratch[SCRATCH_FLOATS];

__device__ __forceinline__ float gelu_f(float x) {
    return 0.5f * x * (1.0f + erff(x * 0.70710678118654752440f));
}

// ---------------------------------------------------------------------------
// Packed f32x2 helpers (sm_103a): 2 exact fp32 FMAs per instruction.
// ---------------------------------------------------------------------------
typedef unsigned long long u64;

__device__ __forceinline__ u64 dup2(float x) {
    u64 r;
    asm("mov.b64 %0, {%1, %1};" : "=l"(r) : "r"(__float_as_uint(x)));
    return r;
}
__device__ __forceinline__ u64 pk(float x, float y) {
    u64 r;
    asm("mov.b64 %0, {%1, %2};" : "=l"(r) : "r"(__float_as_uint(x)), "r"(__float_as_uint(y)));
    return r;
}
__device__ __forceinline__ float2 unpk(u64 v) {
    unsigned lo, hi;
    asm("mov.b64 {%0, %1}, %2;" : "=r"(lo), "=r"(hi) : "l"(v));
    return make_float2(__uint_as_float(lo), __uint_as_float(hi));
}
__device__ __forceinline__ u64 fma2(u64 a, u64 b, u64 c) {
    u64 r;
    asm("fma.rn.f32x2 %0, %1, %2, %3;" : "=l"(r) : "l"(a), "l"(b), "l"(c));
    return r;
}

// ---------------------------------------------------------------------------
// Generic tiled 3x3 conv, pad=1. Block (32,4)=128 thr, out tile 32x16,
// 4 rows/thread, CO_CHUNK co per z-slice. ALL weights prestaged in smem
// (k-major, co-paired for LDS.64 feeding fma.rn.f32x2).
// ---------------------------------------------------------------------------
template<int CI, int CO_CHUNK, bool GELU, bool NHWC>
__global__ __launch_bounds__(128)
void conv3x3_kernel(const float* __restrict__ in, const float* __restrict__ w,
                    const float* __restrict__ bias, float* __restrict__ out,
                    int CO, int H, int W)
{
    constexpr int NW = CI * 9 * CO_CHUNK;
    constexpr int PAIRS = CO_CHUNK / 2;
    __shared__ float s_in[18][34];
    __shared__ __align__(8) float s_w[NW];

    const int tx = threadIdx.x, ty = threadIdx.y;
    const int tid = ty * 32 + tx;
    const int chunks = CO / CO_CHUNK;
    const int b = blockIdx.z / chunks;
    const int coBase = (blockIdx.z % chunks) * CO_CHUNK;
    const int x0 = blockIdx.x * 32;
    const int y0 = blockIdx.y * 16;

    // Prestage ALL weights once: layout [(ci*9 + k)*CO_CHUNK + c]
    for (int i = tid; i < NW; i += 128) {
        int c = i % CO_CHUNK;
        int k = (i / CO_CHUNK) % 9;
        int ci = i / (9 * CO_CHUNK);
        s_w[i] = w[((size_t)(coBase + c) * CI + ci) * 9 + k];
    }

    u64 acc2[PAIRS][4];
#pragma unroll
    for (int c2 = 0; c2 < PAIRS; c2++)
#pragma unroll
        for (int r = 0; r < 4; r++) acc2[c2][r] = 0ULL;

    const float* inb = in + (size_t)b * CI * H * W;

    for (int ci = 0; ci < CI; ci++) {
        const float* inc = inb + (size_t)ci * H * W;
        for (int idx = tid; idx < 18 * 34; idx += 128) {
            int row = idx / 34, col = idx % 34;
            int gy = y0 + row - 1, gx = x0 + col - 1;
            float v = 0.f;
            if (gy >= 0 && gy < H && gx >= 0 && gx < W) v = inc[(size_t)gy * W + gx];
            s_in[row][col] = v;
        }
        __syncthreads();

        u64 vd[6][3];
#pragma unroll
        for (int rr = 0; rr < 6; rr++)
#pragma unroll
            for (int cc = 0; cc < 3; cc++) vd[rr][cc] = dup2(s_in[ty * 4 + rr][tx + cc]);

        const u64* wp = (const u64*)(s_w + ci * 9 * CO_CHUNK);
#pragma unroll
        for (int k = 0; k < 9; k++) {
            const int ky = k / 3, kx = k % 3;
#pragma unroll
            for (int c2 = 0; c2 < PAIRS; c2++) {
                u64 w2 = wp[k * PAIRS + c2];
                acc2[c2][0] = fma2(vd[0 + ky][kx], w2, acc2[c2][0]);
                acc2[c2][1] = fma2(vd[1 + ky][kx], w2, acc2[c2][1]);
                acc2[c2][2] = fma2(vd[2 + ky][kx], w2, acc2[c2][2]);
                acc2[c2][3] = fma2(vd[3 + ky][kx], w2, acc2[c2][3]);
            }
        }
        __syncthreads();
    }

    const int x = x0 + tx;
#pragma unroll
    for (int c2 = 0; c2 < PAIRS; c2++) {
        const float bvx = bias[coBase + 2 * c2];
        const float bvy = bias[coBase + 2 * c2 + 1];
#pragma unroll
        for (int r = 0; r < 4; r++) {
            const int y = y0 + ty * 4 + r;
            float2 a = unpk(acc2[c2][r]);
            a.x += bvx; a.y += bvy;
            if (GELU) { a.x = gelu_f(a.x); a.y = gelu_f(a.y); }
            if (NHWC) {
                *(float2*)&out[(((size_t)b * H + y) * W + x) * CO + coBase + 2 * c2] = a;
            } else {
                out[(((size_t)b * CO + coBase + 2 * c2) * H + y) * W + x] = a.x;
                out[(((size_t)b * CO + coBase + 2 * c2 + 1) * H + y) * W + x] = a.y;
            }
        }
    }
}

// ---------------------------------------------------------------------------
// All 4 band convs merged into ONE launch (wave-quantization fix):
// 2048 blocks instead of 4x512. CI=64, CO=64, CO_CHUNK=16, NHWC out.
// ---------------------------------------------------------------------------
struct Band4 {
    const float* in[4];
    const float* w[4];
    const float* bias[4];
};

__global__ __launch_bounds__(128)
void band_conv_kernel(Band4 a, float* __restrict__ outBase)
{
    __shared__ float s_in[18][34];
    __shared__ __align__(8) float s_w[9216];

    const int tx = threadIdx.x, ty = threadIdx.y;
    const int tid = ty * 32 + tx;
    const int band = blockIdx.z >> 4;
    const int bz = blockIdx.z & 15;
    const int b = bz >> 2;
    const int coBase = (bz & 3) * 16;
    const int x0 = blockIdx.x * 32;
    const int y0 = blockIdx.y * 16;

    const float* in = a.in[band];
    const float* w = a.w[band];
    const float* bias = a.bias[band];
    float* out = outBase + (size_t)band * BANDSZ;

    for (int i = tid; i < 9216; i += 128) {
        int c = i & 15;
        int k = (i >> 4) % 9;
        int ci = i / 144;
        s_w[i] = w[((size_t)(coBase + c) * 64 + ci) * 9 + k];
    }

    u64 acc2[8][4];
#pragma unroll
    for (int c2 = 0; c2 < 8; c2++)
#pragma unroll
        for (int r = 0; r < 4; r++) acc2[c2][r] = 0ULL;

    const float* inb = in + (size_t)b * 64 * H2 * W2;

    for (int ci = 0; ci < 64; ci++) {
        const float* inc = inb + (size_t)ci * H2 * W2;
        for (int idx = tid; idx < 18 * 34; idx += 128) {
            int row = idx / 34, col = idx % 34;
            int gy = y0 + row - 1, gx = x0 + col - 1;
            float v = 0.f;
            if (gy >= 0 && gy < H2 && gx >= 0 && gx < W2) v = inc[(size_t)gy * W2 + gx];
            s_in[row][col] = v;
        }
        __syncthreads();

        u64 vd[6][3];
#pragma unroll
        for (int rr = 0; rr < 6; rr++)
#pragma unroll
            for (int cc = 0; cc < 3; cc++) vd[rr][cc] = dup2(s_in[ty * 4 + rr][tx + cc]);

        const u64* wp = (const u64*)(s_w + ci * 144);
#pragma unroll
        for (int k = 0; k < 9; k++) {
            const int ky = k / 3, kx = k % 3;
#pragma unroll
            for (int c2 = 0; c2 < 8; c2++) {
                u64 w2 = wp[k * 8 + c2];
                acc2[c2][0] = fma2(vd[0 + ky][kx], w2, acc2[c2][0]);
                acc2[c2][1] = fma2(vd[1 + ky][kx], w2, acc2[c2][1]);
                acc2[c2][2] = fma2(vd[2 + ky][kx], w2, acc2[c2][2]);
                acc2[c2][3] = fma2(vd[3 + ky][kx], w2, acc2[c2][3]);
            }
        }
        __syncthreads();
    }

    const int x = x0 + tx;
#pragma unroll
    for (int c2 = 0; c2 < 8; c2++) {
        const float bvx = bias[coBase + 2 * c2];
        const float bvy = bias[coBase + 2 * c2 + 1];
#pragma unroll
        for (int r = 0; r < 4; r++) {
            const int y = y0 + ty * 4 + r;
            float2 a = unpk(acc2[c2][r]);
            a.x += bvx; a.y += bvy;
            *(float2*)&out[(((size_t)b * H2 + y) * W2 + x) * 64 + coBase + 2 * c2] = a;
        }
    }
}

// ---------------------------------------------------------------------------
// Haar DWT (stride-2).
// ---------------------------------------------------------------------------
__global__ void dwt_kernel(const float* __restrict__ R, float* __restrict__ ll,
                           float* __restrict__ lh, float* __restrict__ hl,
                           float* __restrict__ hh)
{
    int idx = blockIdx.x * 256 + threadIdx.x;
    if (idx >= BB * CC * H2 * W2) return;
    int x = idx & 127;
    int y = (idx >> 7) & 127;
    int bc = idx >> 14;
    const float2* R2 = (const float2*)R;
    size_t r0 = ((size_t)bc * 256 + 2 * y) * 128 + x;
    float2 ab = R2[r0];
    float2 cd = R2[r0 + 128];
    const float S = 0.70710678118654752440f;
    float xl0 = (ab.x + ab.y) * S, xh0 = (ab.y - ab.x) * S;
    float xl1 = (cd.x + cd.y) * S, xh1 = (cd.y - cd.x) * S;
    ll[idx] = (xl0 + xl1) * S;
    lh[idx] = (xl1 - xl0) * S;
    hl[idx] = (xh0 + xh1) * S;
    hh[idx] = (xh1 - xh0) * S;
}

// ---------------------------------------------------------------------------
// 2x2 avg-pool of conv2 output, then tanh * 0.25
// ---------------------------------------------------------------------------
__global__ void pool_tanh_kernel(const float* __restrict__ in, float* __restrict__ out)
{
    int idx = blockIdx.x * 256 + threadIdx.x;
    if (idx >= BB * 6 * H2 * W2) return;
    int x = idx & 127;
    int y = (idx >> 7) & 127;
    int bc = idx >> 14;
    const float2* in2 = (const float2*)in;
    size_t r0 = ((size_t)bc * 256 + 2 * y) * 128 + x;
    float2 ab = in2[r0];
    float2 cd = in2[r0 + 128];
    float s = 0.25f * (((ab.x + ab.y) + cd.x) + cd.y);
    out[idx] = tanhf(s) * 0.25f;
}

// ---------------------------------------------------------------------------
// Bilinear grid-sample, padding=reflection, align_corners=True.
// ---------------------------------------------------------------------------
__global__ void deform_kernel(const float* __restrict__ lh, const float* __restrict__ hl,
                              const float* __restrict__ hh, const float* __restrict__ offp,
                              float* __restrict__ zlh, float* __restrict__ zhl,
                              float* __restrict__ zhh)
{
    int pix = blockIdx.x * 256 + threadIdx.x;
    if (pix >= NPIX) return;
    int band = blockIdx.y;
    int x = pix & 127, y = (pix >> 7) & 127, b = pix >> 14;
    const float* in;
    float* out;
    if (band == 0)      { in = lh; out = zlh; }
    else if (band == 1) { in = hl; out = zhl; }
    else                { in = hh; out = zhh; }

    size_t obase = (((size_t)b * 6 + band * 2) * 128 + y) * 128 + x;
    float ox = offp[obase];
    float oy = offp[obase + 16384];
    float ix = (float)x + ox * 63.5f;
    float iy = (float)y + oy * 63.5f;
    float t;
    t = fabsf(ix); t = fmodf(t, 254.f); ix = (t > 127.f) ? (254.f - t) : t;
    t = fabsf(iy); t = fmodf(t, 254.f); iy = (t > 127.f) ? (254.f - t) : t;
    float xf = floorf(ix), yf = floorf(iy);
    float wx = ix - xf, wy = iy - yf;
    int ax0 = min(max((int)xf, 0), 127), ax1 = min(ax0 + 1, 127);
    int ay0 = min(max((int)yf, 0), 127), ay1 = min(ay0 + 1, 127);
    float w00 = (1.f - wx) * (1.f - wy);
    float w01 = wx * (1.f - wy);
    float w10 = (1.f - wx) * wy;
    float w11 = wx * wy;

    const float* inb = in + (size_t)b * 64 * 16384;
    float* outb = out + (size_t)b * 64 * 16384 + (size_t)y * 128 + x;
    int r0 = ay0 * 128, r1 = ay1 * 128;
#pragma unroll 4
    for (int c = 0; c < 64; c++) {
        const float* pc = inb + (size_t)c * 16384;
        float v = pc[r0 + ax0] * w00 + pc[r0 + ax1] * w01 +
                  pc[r1 + ax0] * w10 + pc[r1 + ax1] * w11;
        outb[(size_t)c * 16384] = v;
    }
}

// ---------------------------------------------------------------------------
// Fused LayerNorm + FFN(64->256 GELU ->64) + residual, f32x2 version.
// 512 threads (16 warps), each warp does 4 pixels.
//  fc1: W1 pre-paired as float2 (j, j+32 per t2-pair) -> LDS.64 + fma2
//  fc2: hb stored transposed [j][p] -> packed-over-p accumulation
// ---------------------------------------------------------------------------
#define LNF_WARPS 16
#define LNF_THREADS 512
#define LN_SMEM_FLOATS (16384 + 16384 + 256 + 64 + 64 + 64 + LNF_WARPS*256 + LNF_WARPS*1024)
#define LN_SMEM_BYTES  (LN_SMEM_FLOATS * 4)

__global__ __launch_bounds__(LNF_THREADS)
void ln_ffn_kernel(const float* in, float* out,
                   const float* __restrict__ lnw, const float* __restrict__ lnb,
                   const float* __restrict__ Wfc1, const float* __restrict__ bfc1,
                   const float* __restrict__ Wfc2, const float* __restrict__ bfc2,
                   int npix, int nchw)
{
    extern __shared__ __align__(16) float sm[];
    float* sW1v = sm;               // 16384: float2 pairs [(i*4+m)*32+lane] = (W1[i][lane+64m], W1[i][lane+64m+32])
    float* sW2  = sW1v + 16384;     // 16384: [j][64]
    float* sb1  = sW2 + 16384;      // 256
    float* sb2  = sb1 + 256;        // 64
    float* slw  = sb2 + 64;         // 64
    float* slb  = slw + 64;         // 64
    float* sZN  = slb + 64;         // 16 warps * 256
    float* sH   = sZN + LNF_WARPS * 256;  // 16 warps * 1024, layout hb[j*4+p]

    const int tid = threadIdx.x;
    for (int i = tid; i < 16384; i += LNF_THREADS) sW2[i] = Wfc2[i];
    {
        float2* w1v = (float2*)sW1v;
        for (int idx = tid; idx < 8192; idx += LNF_THREADS) {
            int lane = idx & 31, m = (idx >> 5) & 3, i = idx >> 7;
            w1v[idx] = make_float2(Wfc1[i * 256 + 64 * m + lane],
                                   Wfc1[i * 256 + 64 * m + 32 + lane]);
        }
    }
    if (tid < 256) sb1[tid] = bfc1[tid];
    if (tid < 64) { sb2[tid] = bfc2[tid]; slw[tid] = lnw[tid]; slb[tid] = lnb[tid]; }
    __syncthreads();

    const int warp = tid >> 5, lane = tid & 31;
    float* zn = sZN + warp * 256;
    float* hb = sH + warp * 1024;
    const u64* w1u = (const u64*)sW1v;
    const float lw0 = slw[lane], lw1 = slw[lane + 32];
    const float lb0 = slb[lane], lb1 = slb[lane + 32];
    const float bo0 = sb2[lane], bo1 = sb2[lane + 32];
    u64 binit[4];
#pragma unroll
    for (int m = 0; m < 4; m++) binit[m] = pk(sb1[lane + 64 * m], sb1[lane + 64 * m + 32]);

    const int task0 = (blockIdx.x * LNF_WARPS + warp) * 4;
    const int tstride = gridDim.x * LNF_WARPS * 4;

    for (int base = task0; base < npix; base += tstride) {
        float za[4][2];
#pragma unroll
        for (int p = 0; p < 4; p++) {
            const int pix = base + p;
            float a0 = in[(size_t)pix * 64 + lane];
            float a1 = in[(size_t)pix * 64 + 32 + lane];
            float s = a0 + a1, sq = a0 * a0 + a1 * a1;
#pragma unroll
            for (int o = 16; o; o >>= 1) {
                s  += __shfl_xor_sync(0xffffffffu, s, o);
                sq += __shfl_xor_sync(0xffffffffu, sq, o);
            }
            float mu = s * 0.015625f;
            float var = sq * 0.015625f - mu * mu;
            float rs = rsqrtf(var + 1e-5f);
            zn[p * 64 + lane]      = (a0 - mu) * rs * lw0 + lb0;
            zn[p * 64 + lane + 32] = (a1 - mu) * rs * lw1 + lb1;
            za[p][0] = a0; za[p][1] = a1;
        }
        __syncwarp();

        // fc1: h2[m][p] = packed (h[lane+64m][p], h[lane+64m+32][p])
        u64 h2[4][4];
#pragma unroll
        for (int m = 0; m < 4; m++)
#pragma unroll
            for (int p = 0; p < 4; p++) h2[m][p] = binit[m];

        for (int i = 0; i < 64; i++) {
            u64 zd0 = dup2(zn[i]);
            u64 zd1 = dup2(zn[64 + i]);
            u64 zd2 = dup2(zn[128 + i]);
            u64 zd3 = dup2(zn[192 + i]);
#pragma unroll
            for (int m = 0; m < 4; m++) {
                u64 w2 = w1u[(i * 4 + m) * 32 + lane];
                h2[m][0] = fma2(zd0, w2, h2[m][0]);
                h2[m][1] = fma2(zd1, w2, h2[m][1]);
                h2[m][2] = fma2(zd2, w2, h2[m][2]);
                h2[m][3] = fma2(zd3, w2, h2[m][3]);
            }
        }

        // GELU + transposed store hb[j*4+p] (p-pairs packed -> STS.64)
#pragma unroll
        for (int m = 0; m < 4; m++) {
            float2 q0 = unpk(h2[m][0]), q1 = unpk(h2[m][1]);
            float2 q2 = unpk(h2[m][2]), q3 = unpk(h2[m][3]);
            int jlo = lane + 64 * m, jhi = jlo + 32;
            *(u64*)&hb[jlo * 4]     = pk(gelu_f(q0.x), gelu_f(q1.x));
            *(u64*)&hb[jlo * 4 + 2] = pk(gelu_f(q2.x), gelu_f(q3.x));
            *(u64*)&hb[jhi * 4]     = pk(gelu_f(q0.y), gelu_f(q1.y));
            *(u64*)&hb[jhi * 4 + 2] = pk(gelu_f(q2.y), gelu_f(q3.y));
        }
        __syncwarp();

        // fc2: accumulate packed over pixel pairs
        u64 f0a = dup2(bo0), f0b = dup2(bo0);
        u64 f1a = dup2(bo1), f1b = dup2(bo1);
#pragma unroll 4
        for (int j = 0; j < 256; j++) {
            u64 w0d = dup2(sW2[j * 64 + lane]);
            u64 w1d = dup2(sW2[j * 64 + lane + 32]);
            u64 h01 = *(const u64*)&hb[j * 4];
            u64 h23 = *(const u64*)&hb[j * 4 + 2];
            f0a = fma2(h01, w0d, f0a); f0b = fma2(h23, w0d, f0b);
            f1a = fma2(h01, w1d, f1a); f1b = fma2(h23, w1d, f1b);
        }
        float2 F0a = unpk(f0a), F0b = unpk(f0b), F1a = unpk(f1a), F1b = unpk(f1b);
        float f0[4] = {F0a.x, F0a.y, F0b.x, F0b.y};
        float f1[4] = {F1a.x, F1a.y, F1b.x, F1b.y};

#pragma unroll
        for (int p = 0; p < 4; p++) {
            const int pix = base + p;
            float o0 = za[p][0] + f0[p];
            float o1 = za[p][1] + f1[p];
            if (nchw) {
                int b = pix >> 14, y = (pix >> 7) & 127, x = pix & 127;
                out[(((size_t)b * 64 + lane) * 128 + y) * 128 + x] = o0;
                out[(((size_t)b * 64 + lane + 32) * 128 + y) * 128 + x] = o1;
            } else {
                out[(size_t)pix * 64 + lane] = o0;
                out[(size_t)pix * 64 + 32 + lane] = o1;
            }
        }
        __syncwarp();
    }
}

// ---------------------------------------------------------------------------
// 1x1 fusion conv: z[64] = fus_w[64][256] @ concat(...) + b.
// ---------------------------------------------------------------------------
#define FUSE_SMEM_FLOATS (256*64 + 64 + 8*4*256)
#define FUSE_SMEM_BYTES  (FUSE_SMEM_FLOATS * 4)

__global__ __launch_bounds__(256)
void fuse_kernel(const float* __restrict__ in0, const float* __restrict__ in1,
                 const float* __restrict__ in2, const float* __restrict__ in3,
                 const float* __restrict__ fw, const float* __restrict__ fb,
                 float* __restrict__ out, int npix)
{
    extern __shared__ float smf[];
    float* sFw = smf;              // [256][64] (k-major, transposed)
    float* sfb = sFw + 16384;      // 64
    float* sV  = sfb + 64;         // 8 warps * 4 px * 256

    const int tid = threadIdx.x;
    for (int i = tid; i < 16384; i += 256) {
        int co = i >> 8, k = i & 255;
        sFw[k * 64 + co] = fw[i];
    }
    if (tid < 64) sfb[tid] = fb[tid];
    __syncthreads();

    const int warp = tid >> 5, lane = tid & 31;
    float* v = sV + warp * 1024;
    const float bo0 = sfb[lane], bo1 = sfb[lane + 32];
    const int task0 = (blockIdx.x * 8 + warp) * 4;
    const int tstride = gridDim.x * 8 * 4;

    for (int base = task0; base < npix; base += tstride) {
#pragma unroll
        for (int p = 0; p < 4; p++) {
            size_t off = (size_t)(base + p) * 64;
            v[p * 256 + 0 * 64 + lane] = in0[off + lane];
            v[p * 256 + 0 * 64 + lane + 32] = in0[off + lane + 32];
            v[p * 256 + 1 * 64 + lane] = in1[off + lane];
            v[p * 256 + 1 * 64 + lane + 32] = in1[off + lane + 32];
            v[p * 256 + 2 * 64 + lane] = in2[off + lane];
            v[p * 256 + 2 * 64 + lane + 32] = in2[off + lane + 32];
            v[p * 256 + 3 * 64 + lane] = in3[off + lane];
            v[p * 256 + 3 * 64 + lane + 32] = in3[off + lane + 32];
        }
        __syncwarp();
        // packed over pixel pairs; weights duplicated per k
        u64 z0a = dup2(bo0), z0b = dup2(bo0), z1a = dup2(bo1), z1b = dup2(bo1);
#pragma unroll 4
        for (int k = 0; k < 256; k++) {
            u64 w0d = dup2(sFw[k * 64 + lane]);
            u64 w1d = dup2(sFw[k * 64 + lane + 32]);
            u64 v01 = pk(v[k], v[256 + k]);
            u64 v23 = pk(v[512 + k], v[768 + k]);
            z0a = fma2(v01, w0d, z0a); z0b = fma2(v23, w0d, z0b);
            z1a = fma2(v01, w1d, z1a); z1b = fma2(v23, w1d, z1b);
        }
        float2 Z0a = unpk(z0a), Z0b = unpk(z0b), Z1a = unpk(z1a), Z1b = unpk(z1b);
        float z0[4] = {Z0a.x, Z0a.y, Z0b.x, Z0b.y};
        float z1[4] = {Z1a.x, Z1a.y, Z1b.x, Z1b.y};
#pragma unroll
        for (int p = 0; p < 4; p++) {
            out[(size_t)(base + p) * 64 + lane] = z0[p];
            out[(size_t)(base + p) * 64 + 32 + lane] = z1[p];
        }
        __syncwarp();
    }
}

// ---------------------------------------------------------------------------
// Launch
// ---------------------------------------------------------------------------
extern "C" void kernel_launch(void* const* d_in, const int* in_sizes, int n_in,
                              void* d_out, int out_size)
{
    const float* R      = (const float*)d_in[0];
    const float* off_w1 = (const float*)d_in[1];
    const float* off_b1 = (const float*)d_in[2];
    const float* off_w2 = (const float*)d_in[3];
    const float* off_b2 = (const float*)d_in[4];
    const float* w_ll   = (const float*)d_in[5];
    const float* b_ll   = (const float*)d_in[6];
    const float* w_lh   = (const float*)d_in[7];
    const float* b_lh   = (const float*)d_in[8];
    const float* w_hl   = (const float*)d_in[9];
    const float* b_hl   = (const float*)d_in[10];
    const float* w_hh   = (const float*)d_in[11];
    const float* b_hh   = (const float*)d_in[12];
    const float* ln_w   = (const float*)d_in[13];
    const float* ln_b   = (const float*)d_in[14];
    const float* ffn_w1 = (const float*)d_in[15];
    const float* ffn_b1 = (const float*)d_in[16];
    const float* ffn_w2 = (const float*)d_in[17];
    const float* ffn_b2 = (const float*)d_in[18];
    const float* fus_w  = (const float*)d_in[19];
    const float* fus_b  = (const float*)d_in[20];
    float* out = (float*)d_out;

    float* S = nullptr;
    cudaGetSymbolAddress((void**)&S, g_scratch);

    float* off1 = S + OFF1;
    float* off2 = S + OFF2;
    float* offp = S + OFFP;
    float* pll = S + LLo;
    float* plh = S + LHo;
    float* phl = S + HLo;
    float* phh = S + HHo;
    float* zlh = S + ZLH;
    float* zhl = S + ZHL;
    float* zhh = S + ZHH;
    float* bc0 = S + BC0;
    float* bc1 = bc0 + BANDSZ;
    float* bc2 = bc1 + BANDSZ;
    float* bc3 = bc2 + BANDSZ;
    float* fz  = S + FZ;

    cudaFuncSetAttribute((const void*)ln_ffn_kernel,
                         cudaFuncAttributeMaxDynamicSharedMemorySize, LN_SMEM_BYTES);
    cudaFuncSetAttribute((const void*)fuse_kernel,
                         cudaFuncAttributeMaxDynamicSharedMemorySize, FUSE_SMEM_BYTES);

    dim3 cblk(32, 4);

    // Offset network
    conv3x3_kernel<64, 16, true,  false><<<dim3(8, 16, 8), cblk>>>(R, off_w1, off_b1, off1, 32, HF, WF);
    conv3x3_kernel<32, 6,  false, false><<<dim3(8, 16, 4), cblk>>>(off1, off_w2, off_b2, off2, 6, HF, WF);
    pool_tanh_kernel<<<(BB * 6 * H2 * W2 + 255) / 256, 256>>>(off2, offp);

    // DWT + deform
    dwt_kernel<<<(BB * CC * H2 * W2 + 255) / 256, 256>>>(R, pll, plh, phl, phh);
    deform_kernel<<<dim3(NPIX / 256, 3), 256>>>(plh, phl, phh, offp, zlh, zhl, zhh);

    // All 4 band convs in one launch (NHWC out, contiguous bands)
    Band4 args;
    args.in[0] = pll;  args.in[1] = zlh;  args.in[2] = zhl;  args.in[3] = zhh;
    args.w[0] = w_ll;  args.w[1] = w_lh;  args.w[2] = w_hl;  args.w[3] = w_hh;
    args.bias[0] = b_ll; args.bias[1] = b_lh; args.bias[2] = b_hl; args.bias[3] = b_hh;
    band_conv_kernel<<<dim3(4, 8, 64), cblk>>>(args, bc0);

    // LN+FFN residual over all 4 bands at once (contiguous NHWC, in-place)
    ln_ffn_kernel<<<148, LNF_THREADS, LN_SMEM_BYTES>>>(bc0, bc0, ln_w, ln_b,
                                                       ffn_w1, ffn_b1, ffn_w2, ffn_b2,
                                                       4 * NPIX, 0);

    // 1x1 fusion conv
    fuse_kernel<<<148, 256, FUSE_SMEM_BYTES>>>(bc0, bc1, bc2, bc3, fus_w, fus_b, fz, NPIX);

    // Final LN+FFN residual, NCHW output
    ln_ffn_kernel<<<148, LNF_THREADS, LN_SMEM_BYTES>>>(fz, out, ln_w, ln_b,
                                                       ffn_w1, ffn_b1, ffn_w2, ffn_b2,
                                                       NPIX, 1);
}

// round 16
// speedup vs baseline: 1.5196x; 1.2808x over previous
#include <cuda_runtime.h>
#include <cstdint>

// ---------------------------------------------------------------------------
// Problem dims
// ---------------------------------------------------------------------------
#define BB 4
#define CC 64
#define HF 256
#define WF 256
#define H2 128
#define W2 128
#define NPIX  (BB*H2*W2)
#define BANDSZ ((size_t)BB*64*H2*W2)

// ---------------------------------------------------------------------------
// Scratch
// ---------------------------------------------------------------------------
static const size_t OFF1 = 0;
static const size_t OFF2 = OFF1 + (size_t)4*32*256*256;
static const size_t OFFP = OFF2 + (size_t)4*6*256*256;
static const size_t LLo  = OFFP + (size_t)4*6*128*128;
static const size_t LHo  = LLo + BANDSZ;
static const size_t HLo  = LHo + BANDSZ;
static const size_t HHo  = HLo + BANDSZ;
static const size_t ZLH  = HHo + BANDSZ;
static const size_t ZHL  = ZLH + BANDSZ;
static const size_t ZHH  = ZHL + BANDSZ;
static const size_t BC0  = ZHH + BANDSZ;
static const size_t FZ   = BC0 + 4*BANDSZ;
static const size_t SCRATCH_FLOATS = FZ + BANDSZ;

__device__ float g_scratch[SCRATCH_FLOATS];

__device__ __forceinline__ float gelu_f(float x) {
    return 0.5f * x * (1.0f + erff(x * 0.70710678118654752440f));
}

// ---------------------------------------------------------------------------
// Packed f32x2 helpers
// ---------------------------------------------------------------------------
typedef unsigned long long u64;

__device__ __forceinline__ u64 dup2(float x) {
    u64 r;
    asm("mov.b64 %0, {%1, %1};" : "=l"(r) : "r"(__float_as_uint(x)));
    return r;
}
__device__ __forceinline__ u64 pk(float x, float y) {
    u64 r;
    asm("mov.b64 %0, {%1, %2};" : "=l"(r) : "r"(__float_as_uint(x)), "r"(__float_as_uint(y)));
    return r;
}
__device__ __forceinline__ float2 unpk(u64 v) {
    unsigned lo, hi;
    asm("mov.b64 {%0, %1}, %2;" : "=r"(lo), "=r"(hi) : "l"(v));
    return make_float2(__uint_as_float(lo), __uint_as_float(hi));
}
__device__ __forceinline__ u64 fma2(u64 a, u64 b, u64 c) {
    u64 r;
    asm("fma.rn.f32x2 %0, %1, %2, %3;" : "=l"(r) : "l"(a), "l"(b), "l"(c));
    return r;
}

// ---------------------------------------------------------------------------
// Generic tiled 3x3 conv, pad=1, DOUBLE-BUFFERED input staging.
// Block (32,4)=128 thr, out tile 32x16, 4 rows/thread, CO_CHUNK co per slice.
// ---------------------------------------------------------------------------
template<int CI, int CO_CHUNK, bool GELU, bool NHWC>
__global__ __launch_bounds__(128)
void conv3x3_kernel(const float* __restrict__ in, const float* __restrict__ w,
                    const float* __restrict__ bias, float* __restrict__ out,
                    int CO, int H, int W)
{
    constexpr int NW = CI * 9 * CO_CHUNK;
    constexpr int PAIRS = CO_CHUNK / 2;
    __shared__ float s_in[2][18][34];
    __shared__ __align__(8) float s_w[NW];

    const int tx = threadIdx.x, ty = threadIdx.y;
    const int tid = ty * 32 + tx;
    const int chunks = CO / CO_CHUNK;
    const int b = blockIdx.z / chunks;
    const int coBase = (blockIdx.z % chunks) * CO_CHUNK;
    const int x0 = blockIdx.x * 32;
    const int y0 = blockIdx.y * 16;

    for (int i = tid; i < NW; i += 128) {
        int c = i % CO_CHUNK;
        int k = (i / CO_CHUNK) % 9;
        int ci = i / (9 * CO_CHUNK);
        s_w[i] = w[((size_t)(coBase + c) * CI + ci) * 9 + k];
    }

    u64 acc2[PAIRS][4];
#pragma unroll
    for (int c2 = 0; c2 < PAIRS; c2++)
#pragma unroll
        for (int r = 0; r < 4; r++) acc2[c2][r] = 0ULL;

    const float* inb = in + (size_t)b * CI * H * W;

    // Precompute this thread's staging coords (same each ci)
    int srow[5], scol[5], sgy[5], sgx[5], sn = 0;
    for (int idx = tid; idx < 18 * 34; idx += 128) {
        srow[sn] = idx / 34; scol[sn] = idx % 34;
        sgy[sn] = y0 + srow[sn] - 1; sgx[sn] = x0 + scol[sn] - 1;
        sn++;
    }

    // Stage ci=0 into buffer 0
    {
        const float* inc = inb;
        for (int j = 0; j < sn; j++) {
            float v = 0.f;
            if (sgy[j] >= 0 && sgy[j] < H && sgx[j] >= 0 && sgx[j] < W)
                v = inc[(size_t)sgy[j] * W + sgx[j]];
            s_in[0][srow[j]][scol[j]] = v;
        }
    }
    __syncthreads();

    for (int ci = 0; ci < CI; ci++) {
        const int cur = ci & 1;

        // Prefetch ci+1 into registers (overlaps with compute below)
        float pf[5];
        if (ci + 1 < CI) {
            const float* inc = inb + (size_t)(ci + 1) * H * W;
            for (int j = 0; j < sn; j++) {
                float v = 0.f;
                if (sgy[j] >= 0 && sgy[j] < H && sgx[j] >= 0 && sgx[j] < W)
                    v = inc[(size_t)sgy[j] * W + sgx[j]];
                pf[j] = v;
            }
        }

        u64 vd[6][3];
#pragma unroll
        for (int rr = 0; rr < 6; rr++)
#pragma unroll
            for (int cc = 0; cc < 3; cc++) vd[rr][cc] = dup2(s_in[cur][ty * 4 + rr][tx + cc]);

        const u64* wp = (const u64*)(s_w + ci * 9 * CO_CHUNK);
#pragma unroll
        for (int k = 0; k < 9; k++) {
            const int ky = k / 3, kx = k % 3;
#pragma unroll
            for (int c2 = 0; c2 < PAIRS; c2++) {
                u64 w2 = wp[k * PAIRS + c2];
                acc2[c2][0] = fma2(vd[0 + ky][kx], w2, acc2[c2][0]);
                acc2[c2][1] = fma2(vd[1 + ky][kx], w2, acc2[c2][1]);
                acc2[c2][2] = fma2(vd[2 + ky][kx], w2, acc2[c2][2]);
                acc2[c2][3] = fma2(vd[3 + ky][kx], w2, acc2[c2][3]);
            }
        }

        if (ci + 1 < CI) {
            for (int j = 0; j < sn; j++)
                s_in[1 - cur][srow[j]][scol[j]] = pf[j];
        }
        __syncthreads();
    }

    const int x = x0 + tx;
#pragma unroll
    for (int c2 = 0; c2 < PAIRS; c2++) {
        const float bvx = bias[coBase + 2 * c2];
        const float bvy = bias[coBase + 2 * c2 + 1];
#pragma unroll
        for (int r = 0; r < 4; r++) {
            const int y = y0 + ty * 4 + r;
            float2 a = unpk(acc2[c2][r]);
            a.x += bvx; a.y += bvy;
            if (GELU) { a.x = gelu_f(a.x); a.y = gelu_f(a.y); }
            if (NHWC) {
                *(float2*)&out[(((size_t)b * H + y) * W + x) * CO + coBase + 2 * c2] = a;
            } else {
                out[(((size_t)b * CO + coBase + 2 * c2) * H + y) * W + x] = a.x;
                out[(((size_t)b * CO + coBase + 2 * c2 + 1) * H + y) * W + x] = a.y;
            }
        }
    }
}

// ---------------------------------------------------------------------------
// All 4 band convs in ONE launch, double-buffered staging.
// ---------------------------------------------------------------------------
struct Band4 {
    const float* in[4];
    const float* w[4];
    const float* bias[4];
};

__global__ __launch_bounds__(128)
void band_conv_kernel(Band4 a, float* __restrict__ outBase)
{
    __shared__ float s_in[2][18][34];
    __shared__ __align__(8) float s_w[9216];

    const int tx = threadIdx.x, ty = threadIdx.y;
    const int tid = ty * 32 + tx;
    const int band = blockIdx.z >> 4;
    const int bz = blockIdx.z & 15;
    const int b = bz >> 2;
    const int coBase = (bz & 3) * 16;
    const int x0 = blockIdx.x * 32;
    const int y0 = blockIdx.y * 16;

    const float* in = a.in[band];
    const float* w = a.w[band];
    const float* bias = a.bias[band];
    float* out = outBase + (size_t)band * BANDSZ;

    for (int i = tid; i < 9216; i += 128) {
        int c = i & 15;
        int k = (i >> 4) % 9;
        int ci = i / 144;
        s_w[i] = w[((size_t)(coBase + c) * 64 + ci) * 9 + k];
    }

    u64 acc2[8][4];
#pragma unroll
    for (int c2 = 0; c2 < 8; c2++)
#pragma unroll
        for (int r = 0; r < 4; r++) acc2[c2][r] = 0ULL;

    const float* inb = in + (size_t)b * 64 * H2 * W2;

    int srow[5], scol[5], sgy[5], sgx[5], sn = 0;
    for (int idx = tid; idx < 18 * 34; idx += 128) {
        srow[sn] = idx / 34; scol[sn] = idx % 34;
        sgy[sn] = y0 + srow[sn] - 1; sgx[sn] = x0 + scol[sn] - 1;
        sn++;
    }

    {
        const float* inc = inb;
        for (int j = 0; j < sn; j++) {
            float v = 0.f;
            if (sgy[j] >= 0 && sgy[j] < H2 && sgx[j] >= 0 && sgx[j] < W2)
                v = inc[(size_t)sgy[j] * W2 + sgx[j]];
            s_in[0][srow[j]][scol[j]] = v;
        }
    }
    __syncthreads();

    for (int ci = 0; ci < 64; ci++) {
        const int cur = ci & 1;

        float pf[5];
        if (ci + 1 < 64) {
            const float* inc = inb + (size_t)(ci + 1) * H2 * W2;
            for (int j = 0; j < sn; j++) {
                float v = 0.f;
                if (sgy[j] >= 0 && sgy[j] < H2 && sgx[j] >= 0 && sgx[j] < W2)
                    v = inc[(size_t)sgy[j] * W2 + sgx[j]];
                pf[j] = v;
            }
        }

        u64 vd[6][3];
#pragma unroll
        for (int rr = 0; rr < 6; rr++)
#pragma unroll
            for (int cc = 0; cc < 3; cc++) vd[rr][cc] = dup2(s_in[cur][ty * 4 + rr][tx + cc]);

        const u64* wp = (const u64*)(s_w + ci * 144);
#pragma unroll
        for (int k = 0; k < 9; k++) {
            const int ky = k / 3, kx = k % 3;
#pragma unroll
            for (int c2 = 0; c2 < 8; c2++) {
                u64 w2 = wp[k * 8 + c2];
                acc2[c2][0] = fma2(vd[0 + ky][kx], w2, acc2[c2][0]);
                acc2[c2][1] = fma2(vd[1 + ky][kx], w2, acc2[c2][1]);
                acc2[c2][2] = fma2(vd[2 + ky][kx], w2, acc2[c2][2]);
                acc2[c2][3] = fma2(vd[3 + ky][kx], w2, acc2[c2][3]);
            }
        }

        if (ci + 1 < 64) {
            for (int j = 0; j < sn; j++)
                s_in[1 - cur][srow[j]][scol[j]] = pf[j];
        }
        __syncthreads();
    }

    const int x = x0 + tx;
#pragma unroll
    for (int c2 = 0; c2 < 8; c2++) {
        const float bvx = bias[coBase + 2 * c2];
        const float bvy = bias[coBase + 2 * c2 + 1];
#pragma unroll
        for (int r = 0; r < 4; r++) {
            const int y = y0 + ty * 4 + r;
            float2 av = unpk(acc2[c2][r]);
            av.x += bvx; av.y += bvy;
            *(float2*)&out[(((size_t)b * H2 + y) * W2 + x) * 64 + coBase + 2 * c2] = av;
        }
    }
}

// ---------------------------------------------------------------------------
// Haar DWT (stride-2).
// ---------------------------------------------------------------------------
__global__ void dwt_kernel(const float* __restrict__ R, float* __restrict__ ll,
                           float* __restrict__ lh, float* __restrict__ hl,
                           float* __restrict__ hh)
{
    int idx = blockIdx.x * 256 + threadIdx.x;
    if (idx >= BB * CC * H2 * W2) return;
    int x = idx & 127;
    int y = (idx >> 7) & 127;
    int bc = idx >> 14;
    const float2* R2 = (const float2*)R;
    size_t r0 = ((size_t)bc * 256 + 2 * y) * 128 + x;
    float2 ab = R2[r0];
    float2 cd = R2[r0 + 128];
    const float S = 0.70710678118654752440f;
    float xl0 = (ab.x + ab.y) * S, xh0 = (ab.y - ab.x) * S;
    float xl1 = (cd.x + cd.y) * S, xh1 = (cd.y - cd.x) * S;
    ll[idx] = (xl0 + xl1) * S;
    lh[idx] = (xl1 - xl0) * S;
    hl[idx] = (xh0 + xh1) * S;
    hh[idx] = (xh1 - xh0) * S;
}

// ---------------------------------------------------------------------------
// 2x2 avg-pool then tanh * 0.25
// ---------------------------------------------------------------------------
__global__ void pool_tanh_kernel(const float* __restrict__ in, float* __restrict__ out)
{
    int idx = blockIdx.x * 256 + threadIdx.x;
    if (idx >= BB * 6 * H2 * W2) return;
    int x = idx & 127;
    int y = (idx >> 7) & 127;
    int bc = idx >> 14;
    const float2* in2 = (const float2*)in;
    size_t r0 = ((size_t)bc * 256 + 2 * y) * 128 + x;
    float2 ab = in2[r0];
    float2 cd = in2[r0 + 128];
    float s = 0.25f * (((ab.x + ab.y) + cd.x) + cd.y);
    out[idx] = tanhf(s) * 0.25f;
}

// ---------------------------------------------------------------------------
// Bilinear grid-sample, reflection, align_corners=True.
// ---------------------------------------------------------------------------
__global__ void deform_kernel(const float* __restrict__ lh, const float* __restrict__ hl,
                              const float* __restrict__ hh, const float* __restrict__ offp,
                              float* __restrict__ zlh, float* __restrict__ zhl,
                              float* __restrict__ zhh)
{
    int pix = blockIdx.x * 256 + threadIdx.x;
    if (pix >= NPIX) return;
    int band = blockIdx.y;
    int x = pix & 127, y = (pix >> 7) & 127, b = pix >> 14;
    const float* in;
    float* out;
    if (band == 0)      { in = lh; out = zlh; }
    else if (band == 1) { in = hl; out = zhl; }
    else                { in = hh; out = zhh; }

    size_t obase = (((size_t)b * 6 + band * 2) * 128 + y) * 128 + x;
    float ox = offp[obase];
    float oy = offp[obase + 16384];
    float ix = (float)x + ox * 63.5f;
    float iy = (float)y + oy * 63.5f;
    float t;
    t = fabsf(ix); t = fmodf(t, 254.f); ix = (t > 127.f) ? (254.f - t) : t;
    t = fabsf(iy); t = fmodf(t, 254.f); iy = (t > 127.f) ? (254.f - t) : t;
    float xf = floorf(ix), yf = floorf(iy);
    float wx = ix - xf, wy = iy - yf;
    int ax0 = min(max((int)xf, 0), 127), ax1 = min(ax0 + 1, 127);
    int ay0 = min(max((int)yf, 0), 127), ay1 = min(ay0 + 1, 127);
    float w00 = (1.f - wx) * (1.f - wy);
    float w01 = wx * (1.f - wy);
    float w10 = (1.f - wx) * wy;
    float w11 = wx * wy;

    const float* inb = in + (size_t)b * 64 * 16384;
    float* outb = out + (size_t)b * 64 * 16384 + (size_t)y * 128 + x;
    int r0 = ay0 * 128, r1 = ay1 * 128;
#pragma unroll 4
    for (int c = 0; c < 64; c++) {
        const float* pc = inb + (size_t)c * 16384;
        float v = pc[r0 + ax0] * w00 + pc[r0 + ax1] * w01 +
                  pc[r1 + ax0] * w10 + pc[r1 + ax1] * w11;
        outb[(size_t)c * 16384] = v;
    }
}

// ---------------------------------------------------------------------------
// Fused LayerNorm + FFN + residual, f32x2, input-prefetched.
// ---------------------------------------------------------------------------
#define LNF_WARPS 16
#define LNF_THREADS 512
#define LN_SMEM_FLOATS (16384 + 16384 + 256 + 64 + 64 + 64 + LNF_WARPS*256 + LNF_WARPS*1024)
#define LN_SMEM_BYTES  (LN_SMEM_FLOATS * 4)

__global__ __launch_bounds__(LNF_THREADS)
void ln_ffn_kernel(const float* in, float* out,
                   const float* __restrict__ lnw, const float* __restrict__ lnb,
                   const float* __restrict__ Wfc1, const float* __restrict__ bfc1,
                   const float* __restrict__ Wfc2, const float* __restrict__ bfc2,
                   int npix, int nchw)
{
    extern __shared__ __align__(16) float sm[];
    float* sW1v = sm;
    float* sW2  = sW1v + 16384;
    float* sb1  = sW2 + 16384;
    float* sb2  = sb1 + 256;
    float* slw  = sb2 + 64;
    float* slb  = slw + 64;
    float* sZN  = slb + 64;
    float* sH   = sZN + LNF_WARPS * 256;

    const int tid = threadIdx.x;
    for (int i = tid; i < 16384; i += LNF_THREADS) sW2[i] = Wfc2[i];
    {
        float2* w1v = (float2*)sW1v;
        for (int idx = tid; idx < 8192; idx += LNF_THREADS) {
            int lane = idx & 31, m = (idx >> 5) & 3, i = idx >> 7;
            w1v[idx] = make_float2(Wfc1[i * 256 + 64 * m + lane],
                                   Wfc1[i * 256 + 64 * m + 32 + lane]);
        }
    }
    if (tid < 256) sb1[tid] = bfc1[tid];
    if (tid < 64) { sb2[tid] = bfc2[tid]; slw[tid] = lnw[tid]; slb[tid] = lnb[tid]; }
    __syncthreads();

    const int warp = tid >> 5, lane = tid & 31;
    float* zn = sZN + warp * 256;
    float* hb = sH + warp * 1024;
    const u64* w1u = (const u64*)sW1v;
    const float lw0 = slw[lane], lw1 = slw[lane + 32];
    const float lb0 = slb[lane], lb1 = slb[lane + 32];
    const float bo0 = sb2[lane], bo1 = sb2[lane + 32];
    u64 binit[4];
#pragma unroll
    for (int m = 0; m < 4; m++) binit[m] = pk(sb1[lane + 64 * m], sb1[lane + 64 * m + 32]);

    const int task0 = (blockIdx.x * LNF_WARPS + warp) * 4;
    const int tstride = gridDim.x * LNF_WARPS * 4;

    float a[4][2];
    if (task0 < npix) {
#pragma unroll
        for (int p = 0; p < 4; p++) {
            a[p][0] = in[(size_t)(task0 + p) * 64 + lane];
            a[p][1] = in[(size_t)(task0 + p) * 64 + 32 + lane];
        }
    }

    for (int base = task0; base < npix; base += tstride) {
        // Prefetch next iteration's inputs early (hide DRAM/L2 latency)
        const int nbase = base + tstride;
        float an[4][2];
        if (nbase < npix) {
#pragma unroll
            for (int p = 0; p < 4; p++) {
                an[p][0] = in[(size_t)(nbase + p) * 64 + lane];
                an[p][1] = in[(size_t)(nbase + p) * 64 + 32 + lane];
            }
        }

        float za[4][2];
#pragma unroll
        for (int p = 0; p < 4; p++) {
            float a0 = a[p][0], a1 = a[p][1];
            float s = a0 + a1, sq = a0 * a0 + a1 * a1;
#pragma unroll
            for (int o = 16; o; o >>= 1) {
                s  += __shfl_xor_sync(0xffffffffu, s, o);
                sq += __shfl_xor_sync(0xffffffffu, sq, o);
            }
            float mu = s * 0.015625f;
            float var = sq * 0.015625f - mu * mu;
            float rs = rsqrtf(var + 1e-5f);
            zn[p * 64 + lane]      = (a0 - mu) * rs * lw0 + lb0;
            zn[p * 64 + lane + 32] = (a1 - mu) * rs * lw1 + lb1;
            za[p][0] = a0; za[p][1] = a1;
        }
        __syncwarp();

        u64 h2[4][4];
#pragma unroll
        for (int m = 0; m < 4; m++)
#pragma unroll
            for (int p = 0; p < 4; p++) h2[m][p] = binit[m];

        for (int i = 0; i < 64; i++) {
            u64 zd0 = dup2(zn[i]);
            u64 zd1 = dup2(zn[64 + i]);
            u64 zd2 = dup2(zn[128 + i]);
            u64 zd3 = dup2(zn[192 + i]);
#pragma unroll
            for (int m = 0; m < 4; m++) {
                u64 w2 = w1u[(i * 4 + m) * 32 + lane];
                h2[m][0] = fma2(zd0, w2, h2[m][0]);
                h2[m][1] = fma2(zd1, w2, h2[m][1]);
                h2[m][2] = fma2(zd2, w2, h2[m][2]);
                h2[m][3] = fma2(zd3, w2, h2[m][3]);
            }
        }

#pragma unroll
        for (int m = 0; m < 4; m++) {
            float2 q0 = unpk(h2[m][0]), q1 = unpk(h2[m][1]);
            float2 q2 = unpk(h2[m][2]), q3 = unpk(h2[m][3]);
            int jlo = lane + 64 * m, jhi = jlo + 32;
            *(u64*)&hb[jlo * 4]     = pk(gelu_f(q0.x), gelu_f(q1.x));
            *(u64*)&hb[jlo * 4 + 2] = pk(gelu_f(q2.x), gelu_f(q3.x));
            *(u64*)&hb[jhi * 4]     = pk(gelu_f(q0.y), gelu_f(q1.y));
            *(u64*)&hb[jhi * 4 + 2] = pk(gelu_f(q2.y), gelu_f(q3.y));
        }
        __syncwarp();

        u64 f0a = dup2(bo0), f0b = dup2(bo0);
        u64 f1a = dup2(bo1), f1b = dup2(bo1);
#pragma unroll 4
        for (int j = 0; j < 256; j++) {
            u64 w0d = dup2(sW2[j * 64 + lane]);
            u64 w1d = dup2(sW2[j * 64 + lane + 32]);
            u64 h01 = *(const u64*)&hb[j * 4];
            u64 h23 = *(const u64*)&hb[j * 4 + 2];
            f0a = fma2(h01, w0d, f0a); f0b = fma2(h23, w0d, f0b);
            f1a = fma2(h01, w1d, f1a); f1b = fma2(h23, w1d, f1b);
        }
        float2 F0a = unpk(f0a), F0b = unpk(f0b), F1a = unpk(f1a), F1b = unpk(f1b);
        float f0[4] = {F0a.x, F0a.y, F0b.x, F0b.y};
        float f1[4] = {F1a.x, F1a.y, F1b.x, F1b.y};

#pragma unroll
        for (int p = 0; p < 4; p++) {
            const int pix = base + p;
            float o0 = za[p][0] + f0[p];
            float o1 = za[p][1] + f1[p];
            if (nchw) {
                int b = pix >> 14, y = (pix >> 7) & 127, x = pix & 127;
                out[(((size_t)b * 64 + lane) * 128 + y) * 128 + x] = o0;
                out[(((size_t)b * 64 + lane + 32) * 128 + y) * 128 + x] = o1;
            } else {
                out[(size_t)pix * 64 + lane] = o0;
                out[(size_t)pix * 64 + 32 + lane] = o1;
            }
        }
#pragma unroll
        for (int p = 0; p < 4; p++) { a[p][0] = an[p][0]; a[p][1] = an[p][1]; }
        __syncwarp();
    }
}

// ---------------------------------------------------------------------------
// 1x1 fusion conv
// ---------------------------------------------------------------------------
#define FUSE_SMEM_FLOATS (256*64 + 64 + 8*4*256)
#define FUSE_SMEM_BYTES  (FUSE_SMEM_FLOATS * 4)

__global__ __launch_bounds__(256)
void fuse_kernel(const float* __restrict__ in0, const float* __restrict__ in1,
                 const float* __restrict__ in2, const float* __restrict__ in3,
                 const float* __restrict__ fw, const float* __restrict__ fb,
                 float* __restrict__ out, int npix)
{
    extern __shared__ float smf[];
    float* sFw = smf;
    float* sfb = sFw + 16384;
    float* sV  = sfb + 64;

    const int tid = threadIdx.x;
    for (int i = tid; i < 16384; i += 256) {
        int co = i >> 8, k = i & 255;
        sFw[k * 64 + co] = fw[i];
    }
    if (tid < 64) sfb[tid] = fb[tid];
    __syncthreads();

    const int warp = tid >> 5, lane = tid & 31;
    float* v = sV + warp * 1024;
    const float bo0 = sfb[lane], bo1 = sfb[lane + 32];
    const int task0 = (blockIdx.x * 8 + warp) * 4;
    const int tstride = gridDim.x * 8 * 4;

    for (int base = task0; base < npix; base += tstride) {
#pragma unroll
        for (int p = 0; p < 4; p++) {
            size_t off = (size_t)(base + p) * 64;
            v[p * 256 + 0 * 64 + lane] = in0[off + lane];
            v[p * 256 + 0 * 64 + lane + 32] = in0[off + lane + 32];
            v[p * 256 + 1 * 64 + lane] = in1[off + lane];
            v[p * 256 + 1 * 64 + lane + 32] = in1[off + lane + 32];
            v[p * 256 + 2 * 64 + lane] = in2[off + lane];
            v[p * 256 + 2 * 64 + lane + 32] = in2[off + lane + 32];
            v[p * 256 + 3 * 64 + lane] = in3[off + lane];
            v[p * 256 + 3 * 64 + lane + 32] = in3[off + lane + 32];
        }
        __syncwarp();
        u64 z0a = dup2(bo0), z0b = dup2(bo0), z1a = dup2(bo1), z1b = dup2(bo1);
#pragma unroll 4
        for (int k = 0; k < 256; k++) {
            u64 w0d = dup2(sFw[k * 64 + lane]);
            u64 w1d = dup2(sFw[k * 64 + lane + 32]);
            u64 v01 = pk(v[k], v[256 + k]);
            u64 v23 = pk(v[512 + k], v[768 + k]);
            z0a = fma2(v01, w0d, z0a); z0b = fma2(v23, w0d, z0b);
            z1a = fma2(v01, w1d, z1a); z1b = fma2(v23, w1d, z1b);
        }
        float2 Z0a = unpk(z0a), Z0b = unpk(z0b), Z1a = unpk(z1a), Z1b = unpk(z1b);
        float z0[4] = {Z0a.x, Z0a.y, Z0b.x, Z0b.y};
        float z1[4] = {Z1a.x, Z1a.y, Z1b.x, Z1b.y};
#pragma unroll
        for (int p = 0; p < 4; p++) {
            out[(size_t)(base + p) * 64 + lane] = z0[p];
            out[(size_t)(base + p) * 64 + 32 + lane] = z1[p];
        }
        __syncwarp();
    }
}

// ---------------------------------------------------------------------------
// Launch
// ---------------------------------------------------------------------------
extern "C" void kernel_launch(void* const* d_in, const int* in_sizes, int n_in,
                              void* d_out, int out_size)
{
    const float* R      = (const float*)d_in[0];
    const float* off_w1 = (const float*)d_in[1];
    const float* off_b1 = (const float*)d_in[2];
    const float* off_w2 = (const float*)d_in[3];
    const float* off_b2 = (const float*)d_in[4];
    const float* w_ll   = (const float*)d_in[5];
    const float* b_ll   = (const float*)d_in[6];
    const float* w_lh   = (const float*)d_in[7];
    const float* b_lh   = (const float*)d_in[8];
    const float* w_hl   = (const float*)d_in[9];
    const float* b_hl   = (const float*)d_in[10];
    const float* w_hh   = (const float*)d_in[11];
    const float* b_hh   = (const float*)d_in[12];
    const float* ln_w   = (const float*)d_in[13];
    const float* ln_b   = (const float*)d_in[14];
    const float* ffn_w1 = (const float*)d_in[15];
    const float* ffn_b1 = (const float*)d_in[16];
    const float* ffn_w2 = (const float*)d_in[17];
    const float* ffn_b2 = (const float*)d_in[18];
    const float* fus_w  = (const float*)d_in[19];
    const float* fus_b  = (const float*)d_in[20];
    float* out = (float*)d_out;

    float* S = nullptr;
    cudaGetSymbolAddress((void**)&S, g_scratch);

    float* off1 = S + OFF1;
    float* off2 = S + OFF2;
    float* offp = S + OFFP;
    float* pll = S + LLo;
    float* plh = S + LHo;
    float* phl = S + HLo;
    float* phh = S + HHo;
    float* zlh = S + ZLH;
    float* zhl = S + ZHL;
    float* zhh = S + ZHH;
    float* bc0 = S + BC0;
    float* bc1 = bc0 + BANDSZ;
    float* bc2 = bc1 + BANDSZ;
    float* bc3 = bc2 + BANDSZ;
    float* fz  = S + FZ;

    cudaFuncSetAttribute((const void*)ln_ffn_kernel,
                         cudaFuncAttributeMaxDynamicSharedMemorySize, LN_SMEM_BYTES);
    cudaFuncSetAttribute((const void*)fuse_kernel,
                         cudaFuncAttributeMaxDynamicSharedMemorySize, FUSE_SMEM_BYTES);

    dim3 cblk(32, 4);

    // Offset network
    conv3x3_kernel<64, 16, true,  false><<<dim3(8, 16, 8), cblk>>>(R, off_w1, off_b1, off1, 32, HF, WF);
    conv3x3_kernel<32, 6,  false, false><<<dim3(8, 16, 4), cblk>>>(off1, off_w2, off_b2, off2, 6, HF, WF);
    pool_tanh_kernel<<<(BB * 6 * H2 * W2 + 255) / 256, 256>>>(off2, offp);

    // DWT + deform
    dwt_kernel<<<(BB * CC * H2 * W2 + 255) / 256, 256>>>(R, pll, plh, phl, phh);
    deform_kernel<<<dim3(NPIX / 256, 3), 256>>>(plh, phl, phh, offp, zlh, zhl, zhh);

    // All 4 band convs in one launch
    Band4 args;
    args.in[0] = pll;  args.in[1] = zlh;  args.in[2] = zhl;  args.in[3] = zhh;
    args.w[0] = w_ll;  args.w[1] = w_lh;  args.w[2] = w_hl;  args.w[3] = w_hh;
    args.bias[0] = b_ll; args.bias[1] = b_lh; args.bias[2] = b_hl; args.bias[3] = b_hh;
    band_conv_kernel<<<dim3(4, 8, 64), cblk>>>(args, bc0);

    // LN+FFN residual over all 4 bands (in-place)
    ln_ffn_kernel<<<148, LNF_THREADS, LN_SMEM_BYTES>>>(bc0, bc0, ln_w, ln_b,
                                                       ffn_w1, ffn_b1, ffn_w2, ffn_b2,
                                                       4 * NPIX, 0);

    // 1x1 fusion conv
    fuse_kernel<<<148, 256, FUSE_SMEM_BYTES>>>(bc0, bc1, bc2, bc3, fus_w, fus_b, fz, NPIX);

    // Final LN+FFN residual, NCHW output
    ln_ffn_kernel<<<148, LNF_THREADS, LN_SMEM_BYTES>>>(fz, out, ln_w, ln_b,
                                                       ffn_w1, ffn_b1, ffn_w2, ffn_b2,
                                                       NPIX, 1);
}

// round 17
// speedup vs baseline: 1.5349x; 1.0101x over previous
#include <cuda_runtime.h>
#include <cstdint>

// ---------------------------------------------------------------------------
// Problem dims
// ---------------------------------------------------------------------------
#define BB 4
#define CC 64
#define HF 256
#define WF 256
#define H2 128
#define W2 128
#define NPIX  (BB*H2*W2)
#define BANDSZ ((size_t)BB*64*H2*W2)

// ---------------------------------------------------------------------------
// Scratch
// ---------------------------------------------------------------------------
static const size_t OFF1 = 0;
static const size_t OFF2 = OFF1 + (size_t)4*32*256*256;
static const size_t OFFP = OFF2 + (size_t)4*6*256*256;
static const size_t LLo  = OFFP + (size_t)4*6*128*128;
static const size_t LHo  = LLo + BANDSZ;
static const size_t HLo  = LHo + BANDSZ;
static const size_t HHo  = HLo + BANDSZ;
static const size_t ZLH  = HHo + BANDSZ;
static const size_t ZHL  = ZLH + BANDSZ;
static const size_t ZHH  = ZHL + BANDSZ;
static const size_t BC0  = ZHH + BANDSZ;
static const size_t FZ   = BC0 + 4*BANDSZ;
static const size_t SCRATCH_FLOATS = FZ + BANDSZ;

__device__ float g_scratch[SCRATCH_FLOATS];

__device__ __forceinline__ float gelu_f(float x) {
    return 0.5f * x * (1.0f + erff(x * 0.70710678118654752440f));
}

// ---------------------------------------------------------------------------
// Packed f32x2 helpers
// ---------------------------------------------------------------------------
typedef unsigned long long u64;

__device__ __forceinline__ u64 dup2(float x) {
    u64 r;
    asm("mov.b64 %0, {%1, %1};" : "=l"(r) : "r"(__float_as_uint(x)));
    return r;
}
__device__ __forceinline__ u64 pk(float x, float y) {
    u64 r;
    asm("mov.b64 %0, {%1, %2};" : "=l"(r) : "r"(__float_as_uint(x)), "r"(__float_as_uint(y)));
    return r;
}
__device__ __forceinline__ float2 unpk(u64 v) {
    unsigned lo, hi;
    asm("mov.b64 {%0, %1}, %2;" : "=r"(lo), "=r"(hi) : "l"(v));
    return make_float2(__uint_as_float(lo), __uint_as_float(hi));
}
__device__ __forceinline__ u64 fma2(u64 a, u64 b, u64 c) {
    u64 r;
    asm("fma.rn.f32x2 %0, %1, %2, %3;" : "=l"(r) : "l"(a), "l"(b), "l"(c));
    return r;
}

// ---------------------------------------------------------------------------
// Generic tiled 3x3 conv, pad=1, DOUBLE-BUFFERED input staging.
// ---------------------------------------------------------------------------
template<int CI, int CO_CHUNK, bool GELU, bool NHWC>
__global__ __launch_bounds__(128)
void conv3x3_kernel(const float* __restrict__ in, const float* __restrict__ w,
                    const float* __restrict__ bias, float* __restrict__ out,
                    int CO, int H, int W)
{
    constexpr int NW = CI * 9 * CO_CHUNK;
    constexpr int PAIRS = CO_CHUNK / 2;
    __shared__ float s_in[2][18][34];
    __shared__ __align__(8) float s_w[NW];

    const int tx = threadIdx.x, ty = threadIdx.y;
    const int tid = ty * 32 + tx;
    const int chunks = CO / CO_CHUNK;
    const int b = blockIdx.z / chunks;
    const int coBase = (blockIdx.z % chunks) * CO_CHUNK;
    const int x0 = blockIdx.x * 32;
    const int y0 = blockIdx.y * 16;

    for (int i = tid; i < NW; i += 128) {
        int c = i % CO_CHUNK;
        int k = (i / CO_CHUNK) % 9;
        int ci = i / (9 * CO_CHUNK);
        s_w[i] = w[((size_t)(coBase + c) * CI + ci) * 9 + k];
    }

    u64 acc2[PAIRS][4];
#pragma unroll
    for (int c2 = 0; c2 < PAIRS; c2++)
#pragma unroll
        for (int r = 0; r < 4; r++) acc2[c2][r] = 0ULL;

    const float* inb = in + (size_t)b * CI * H * W;

    int srow[5], scol[5], sgy[5], sgx[5], sn = 0;
    for (int idx = tid; idx < 18 * 34; idx += 128) {
        srow[sn] = idx / 34; scol[sn] = idx % 34;
        sgy[sn] = y0 + srow[sn] - 1; sgx[sn] = x0 + scol[sn] - 1;
        sn++;
    }

    {
        const float* inc = inb;
        for (int j = 0; j < sn; j++) {
            float v = 0.f;
            if (sgy[j] >= 0 && sgy[j] < H && sgx[j] >= 0 && sgx[j] < W)
                v = inc[(size_t)sgy[j] * W + sgx[j]];
            s_in[0][srow[j]][scol[j]] = v;
        }
    }
    __syncthreads();

    for (int ci = 0; ci < CI; ci++) {
        const int cur = ci & 1;

        float pf[5];
        if (ci + 1 < CI) {
            const float* inc = inb + (size_t)(ci + 1) * H * W;
            for (int j = 0; j < sn; j++) {
                float v = 0.f;
                if (sgy[j] >= 0 && sgy[j] < H && sgx[j] >= 0 && sgx[j] < W)
                    v = inc[(size_t)sgy[j] * W + sgx[j]];
                pf[j] = v;
            }
        }

        u64 vd[6][3];
#pragma unroll
        for (int rr = 0; rr < 6; rr++)
#pragma unroll
            for (int cc = 0; cc < 3; cc++) vd[rr][cc] = dup2(s_in[cur][ty * 4 + rr][tx + cc]);

        const u64* wp = (const u64*)(s_w + ci * 9 * CO_CHUNK);
#pragma unroll
        for (int k = 0; k < 9; k++) {
            const int ky = k / 3, kx = k % 3;
#pragma unroll
            for (int c2 = 0; c2 < PAIRS; c2++) {
                u64 w2 = wp[k * PAIRS + c2];
                acc2[c2][0] = fma2(vd[0 + ky][kx], w2, acc2[c2][0]);
                acc2[c2][1] = fma2(vd[1 + ky][kx], w2, acc2[c2][1]);
                acc2[c2][2] = fma2(vd[2 + ky][kx], w2, acc2[c2][2]);
                acc2[c2][3] = fma2(vd[3 + ky][kx], w2, acc2[c2][3]);
            }
        }

        if (ci + 1 < CI) {
            for (int j = 0; j < sn; j++)
                s_in[1 - cur][srow[j]][scol[j]] = pf[j];
        }
        __syncthreads();
    }

    const int x = x0 + tx;
#pragma unroll
    for (int c2 = 0; c2 < PAIRS; c2++) {
        const float bvx = bias[coBase + 2 * c2];
        const float bvy = bias[coBase + 2 * c2 + 1];
#pragma unroll
        for (int r = 0; r < 4; r++) {
            const int y = y0 + ty * 4 + r;
            float2 a = unpk(acc2[c2][r]);
            a.x += bvx; a.y += bvy;
            if (GELU) { a.x = gelu_f(a.x); a.y = gelu_f(a.y); }
            if (NHWC) {
                *(float2*)&out[(((size_t)b * H + y) * W + x) * CO + coBase + 2 * c2] = a;
            } else {
                out[(((size_t)b * CO + coBase + 2 * c2) * H + y) * W + x] = a.x;
                out[(((size_t)b * CO + coBase + 2 * c2 + 1) * H + y) * W + x] = a.y;
            }
        }
    }
}

// ---------------------------------------------------------------------------
// All 4 band convs in ONE launch, double-buffered staging.
// ---------------------------------------------------------------------------
struct Band4 {
    const float* in[4];
    const float* w[4];
    const float* bias[4];
};

__global__ __launch_bounds__(128)
void band_conv_kernel(Band4 a, float* __restrict__ outBase)
{
    __shared__ float s_in[2][18][34];
    __shared__ __align__(8) float s_w[9216];

    const int tx = threadIdx.x, ty = threadIdx.y;
    const int tid = ty * 32 + tx;
    const int band = blockIdx.z >> 4;
    const int bz = blockIdx.z & 15;
    const int b = bz >> 2;
    const int coBase = (bz & 3) * 16;
    const int x0 = blockIdx.x * 32;
    const int y0 = blockIdx.y * 16;

    const float* in = a.in[band];
    const float* w = a.w[band];
    const float* bias = a.bias[band];
    float* out = outBase + (size_t)band * BANDSZ;

    for (int i = tid; i < 9216; i += 128) {
        int c = i & 15;
        int k = (i >> 4) % 9;
        int ci = i / 144;
        s_w[i] = w[((size_t)(coBase + c) * 64 + ci) * 9 + k];
    }

    u64 acc2[8][4];
#pragma unroll
    for (int c2 = 0; c2 < 8; c2++)
#pragma unroll
        for (int r = 0; r < 4; r++) acc2[c2][r] = 0ULL;

    const float* inb = in + (size_t)b * 64 * H2 * W2;

    int srow[5], scol[5], sgy[5], sgx[5], sn = 0;
    for (int idx = tid; idx < 18 * 34; idx += 128) {
        srow[sn] = idx / 34; scol[sn] = idx % 34;
        sgy[sn] = y0 + srow[sn] - 1; sgx[sn] = x0 + scol[sn] - 1;
        sn++;
    }

    {
        const float* inc = inb;
        for (int j = 0; j < sn; j++) {
            float v = 0.f;
            if (sgy[j] >= 0 && sgy[j] < H2 && sgx[j] >= 0 && sgx[j] < W2)
                v = inc[(size_t)sgy[j] * W2 + sgx[j]];
            s_in[0][srow[j]][scol[j]] = v;
        }
    }
    __syncthreads();

    for (int ci = 0; ci < 64; ci++) {
        const int cur = ci & 1;

        float pf[5];
        if (ci + 1 < 64) {
            const float* inc = inb + (size_t)(ci + 1) * H2 * W2;
            for (int j = 0; j < sn; j++) {
                float v = 0.f;
                if (sgy[j] >= 0 && sgy[j] < H2 && sgx[j] >= 0 && sgx[j] < W2)
                    v = inc[(size_t)sgy[j] * W2 + sgx[j]];
                pf[j] = v;
            }
        }

        u64 vd[6][3];
#pragma unroll
        for (int rr = 0; rr < 6; rr++)
#pragma unroll
            for (int cc = 0; cc < 3; cc++) vd[rr][cc] = dup2(s_in[cur][ty * 4 + rr][tx + cc]);

        const u64* wp = (const u64*)(s_w + ci * 144);
#pragma unroll
        for (int k = 0; k < 9; k++) {
            const int ky = k / 3, kx = k % 3;
#pragma unroll
            for (int c2 = 0; c2 < 8; c2++) {
                u64 w2 = wp[k * 8 + c2];
                acc2[c2][0] = fma2(vd[0 + ky][kx], w2, acc2[c2][0]);
                acc2[c2][1] = fma2(vd[1 + ky][kx], w2, acc2[c2][1]);
                acc2[c2][2] = fma2(vd[2 + ky][kx], w2, acc2[c2][2]);
                acc2[c2][3] = fma2(vd[3 + ky][kx], w2, acc2[c2][3]);
            }
        }

        if (ci + 1 < 64) {
            for (int j = 0; j < sn; j++)
                s_in[1 - cur][srow[j]][scol[j]] = pf[j];
        }
        __syncthreads();
    }

    const int x = x0 + tx;
#pragma unroll
    for (int c2 = 0; c2 < 8; c2++) {
        const float bvx = bias[coBase + 2 * c2];
        const float bvy = bias[coBase + 2 * c2 + 1];
#pragma unroll
        for (int r = 0; r < 4; r++) {
            const int y = y0 + ty * 4 + r;
            float2 av = unpk(acc2[c2][r]);
            av.x += bvx; av.y += bvy;
            *(float2*)&out[(((size_t)b * H2 + y) * W2 + x) * 64 + coBase + 2 * c2] = av;
        }
    }
}

// ---------------------------------------------------------------------------
// Haar DWT (stride-2).
// ---------------------------------------------------------------------------
__global__ void dwt_kernel(const float* __restrict__ R, float* __restrict__ ll,
                           float* __restrict__ lh, float* __restrict__ hl,
                           float* __restrict__ hh)
{
    int idx = blockIdx.x * 256 + threadIdx.x;
    if (idx >= BB * CC * H2 * W2) return;
    int x = idx & 127;
    int y = (idx >> 7) & 127;
    int bc = idx >> 14;
    const float2* R2 = (const float2*)R;
    size_t r0 = ((size_t)bc * 256 + 2 * y) * 128 + x;
    float2 ab = R2[r0];
    float2 cd = R2[r0 + 128];
    const float S = 0.70710678118654752440f;
    float xl0 = (ab.x + ab.y) * S, xh0 = (ab.y - ab.x) * S;
    float xl1 = (cd.x + cd.y) * S, xh1 = (cd.y - cd.x) * S;
    ll[idx] = (xl0 + xl1) * S;
    lh[idx] = (xl1 - xl0) * S;
    hl[idx] = (xh0 + xh1) * S;
    hh[idx] = (xh1 - xh0) * S;
}

// ---------------------------------------------------------------------------
// 2x2 avg-pool then tanh * 0.25
// ---------------------------------------------------------------------------
__global__ void pool_tanh_kernel(const float* __restrict__ in, float* __restrict__ out)
{
    int idx = blockIdx.x * 256 + threadIdx.x;
    if (idx >= BB * 6 * H2 * W2) return;
    int x = idx & 127;
    int y = (idx >> 7) & 127;
    int bc = idx >> 14;
    const float2* in2 = (const float2*)in;
    size_t r0 = ((size_t)bc * 256 + 2 * y) * 128 + x;
    float2 ab = in2[r0];
    float2 cd = in2[r0 + 128];
    float s = 0.25f * (((ab.x + ab.y) + cd.x) + cd.y);
    out[idx] = tanhf(s) * 0.25f;
}

// ---------------------------------------------------------------------------
// Bilinear grid-sample, reflection, align_corners=True.
// ---------------------------------------------------------------------------
__global__ void deform_kernel(const float* __restrict__ lh, const float* __restrict__ hl,
                              const float* __restrict__ hh, const float* __restrict__ offp,
                              float* __restrict__ zlh, float* __restrict__ zhl,
                              float* __restrict__ zhh)
{
    int pix = blockIdx.x * 256 + threadIdx.x;
    if (pix >= NPIX) return;
    int band = blockIdx.y;
    int x = pix & 127, y = (pix >> 7) & 127, b = pix >> 14;
    const float* in;
    float* out;
    if (band == 0)      { in = lh; out = zlh; }
    else if (band == 1) { in = hl; out = zhl; }
    else                { in = hh; out = zhh; }

    size_t obase = (((size_t)b * 6 + band * 2) * 128 + y) * 128 + x;
    float ox = offp[obase];
    float oy = offp[obase + 16384];
    float ix = (float)x + ox * 63.5f;
    float iy = (float)y + oy * 63.5f;
    float t;
    t = fabsf(ix); t = fmodf(t, 254.f); ix = (t > 127.f) ? (254.f - t) : t;
    t = fabsf(iy); t = fmodf(t, 254.f); iy = (t > 127.f) ? (254.f - t) : t;
    float xf = floorf(ix), yf = floorf(iy);
    float wx = ix - xf, wy = iy - yf;
    int ax0 = min(max((int)xf, 0), 127), ax1 = min(ax0 + 1, 127);
    int ay0 = min(max((int)yf, 0), 127), ay1 = min(ay0 + 1, 127);
    float w00 = (1.f - wx) * (1.f - wy);
    float w01 = wx * (1.f - wy);
    float w10 = (1.f - wx) * wy;
    float w11 = wx * wy;

    const float* inb = in + (size_t)b * 64 * 16384;
    float* outb = out + (size_t)b * 64 * 16384 + (size_t)y * 128 + x;
    int r0 = ay0 * 128, r1 = ay1 * 128;
#pragma unroll 4
    for (int c = 0; c < 64; c++) {
        const float* pc = inb + (size_t)c * 16384;
        float v = pc[r0 + ax0] * w00 + pc[r0 + ax1] * w01 +
                  pc[r1 + ax0] * w10 + pc[r1 + ax1] * w11;
        outb[(size_t)c * 16384] = v;
    }
}

// ---------------------------------------------------------------------------
// Fused LayerNorm + FFN + residual, f32x2, vectorized-LDS version.
//  zn stored transposed [i][4px] -> 1 broadcast LDS.128 per i in fc1
//  W2 pre-paired (o, o+32)      -> 1 LDS.64 per j in fc2
//  hb read as ulonglong2        -> 1 broadcast LDS.128 per j in fc2
// ---------------------------------------------------------------------------
#define LNF_WARPS 16
#define LNF_THREADS 512
#define LN_SMEM_FLOATS (16384 + 16384 + 256 + 64 + 64 + 64 + LNF_WARPS*256 + LNF_WARPS*1024)
#define LN_SMEM_BYTES  (LN_SMEM_FLOATS * 4)

__global__ __launch_bounds__(LNF_THREADS)
void ln_ffn_kernel(const float* in, float* out,
                   const float* __restrict__ lnw, const float* __restrict__ lnb,
                   const float* __restrict__ Wfc1, const float* __restrict__ bfc1,
                   const float* __restrict__ Wfc2, const float* __restrict__ bfc2,
                   int npix, int nchw)
{
    extern __shared__ __align__(16) float sm[];
    float* sW1v = sm;               // 16384: fc1 pairs [(i*4+m)*32+lane]
    float* sW2  = sW1v + 16384;     // 16384: fc2 pairs [j*32+lane] = (W2[j][lane], W2[j][lane+32])
    float* sb1  = sW2 + 16384;
    float* sb2  = sb1 + 256;
    float* slw  = sb2 + 64;
    float* slb  = slw + 64;
    float* sZN  = slb + 64;          // 16 warps * 256, transposed [i][4]
    float* sH   = sZN + LNF_WARPS * 256;  // 16 warps * 1024, [j][4]

    const int tid = threadIdx.x;
    {
        float2* w1v = (float2*)sW1v;
        float2* w2p = (float2*)sW2;
        for (int idx = tid; idx < 8192; idx += LNF_THREADS) {
            int lane = idx & 31, m = (idx >> 5) & 3, i = idx >> 7;
            w1v[idx] = make_float2(Wfc1[i * 256 + 64 * m + lane],
                                   Wfc1[i * 256 + 64 * m + 32 + lane]);
            int j = idx >> 5;
            w2p[idx] = make_float2(Wfc2[j * 64 + lane], Wfc2[j * 64 + lane + 32]);
        }
    }
    if (tid < 256) sb1[tid] = bfc1[tid];
    if (tid < 64) { sb2[tid] = bfc2[tid]; slw[tid] = lnw[tid]; slb[tid] = lnb[tid]; }
    __syncthreads();

    const int warp = tid >> 5, lane = tid & 31;
    float* zn = sZN + warp * 256;
    float* hb = sH + warp * 1024;
    const u64* w1u = (const u64*)sW1v;
    const u64* w2u = (const u64*)sW2;
    const float lw0 = slw[lane], lw1 = slw[lane + 32];
    const float lb0 = slb[lane], lb1 = slb[lane + 32];
    const float bo0 = sb2[lane], bo1 = sb2[lane + 32];
    u64 binit[4];
#pragma unroll
    for (int m = 0; m < 4; m++) binit[m] = pk(sb1[lane + 64 * m], sb1[lane + 64 * m + 32]);

    const int task0 = (blockIdx.x * LNF_WARPS + warp) * 4;
    const int tstride = gridDim.x * LNF_WARPS * 4;

    float a[4][2];
    if (task0 < npix) {
#pragma unroll
        for (int p = 0; p < 4; p++) {
            a[p][0] = in[(size_t)(task0 + p) * 64 + lane];
            a[p][1] = in[(size_t)(task0 + p) * 64 + 32 + lane];
        }
    }

    for (int base = task0; base < npix; base += tstride) {
        const int nbase = base + tstride;
        float an[4][2];
        if (nbase < npix) {
#pragma unroll
            for (int p = 0; p < 4; p++) {
                an[p][0] = in[(size_t)(nbase + p) * 64 + lane];
                an[p][1] = in[(size_t)(nbase + p) * 64 + 32 + lane];
            }
        }

        float za[4][2];
        float zn0[4], zn1[4];
#pragma unroll
        for (int p = 0; p < 4; p++) {
            float a0 = a[p][0], a1 = a[p][1];
            float s = a0 + a1, sq = a0 * a0 + a1 * a1;
#pragma unroll
            for (int o = 16; o; o >>= 1) {
                s  += __shfl_xor_sync(0xffffffffu, s, o);
                sq += __shfl_xor_sync(0xffffffffu, sq, o);
            }
            float mu = s * 0.015625f;
            float var = sq * 0.015625f - mu * mu;
            float rs = rsqrtf(var + 1e-5f);
            zn0[p] = (a0 - mu) * rs * lw0 + lb0;
            zn1[p] = (a1 - mu) * rs * lw1 + lb1;
            za[p][0] = a0; za[p][1] = a1;
        }
        // transposed store: zn[i*4 + p]
        *(u64*)&zn[lane * 4]            = pk(zn0[0], zn0[1]);
        *(u64*)&zn[lane * 4 + 2]        = pk(zn0[2], zn0[3]);
        *(u64*)&zn[(lane + 32) * 4]     = pk(zn1[0], zn1[1]);
        *(u64*)&zn[(lane + 32) * 4 + 2] = pk(zn1[2], zn1[3]);
        __syncwarp();

        u64 h2[4][4];
#pragma unroll
        for (int m = 0; m < 4; m++)
#pragma unroll
            for (int p = 0; p < 4; p++) h2[m][p] = binit[m];

        for (int i = 0; i < 64; i++) {
            ulonglong2 zv = *(const ulonglong2*)&zn[i * 4];  // 1 LDS.128 broadcast
            float2 zab = unpk(zv.x), zcd = unpk(zv.y);
            u64 zd0 = dup2(zab.x), zd1 = dup2(zab.y);
            u64 zd2 = dup2(zcd.x), zd3 = dup2(zcd.y);
#pragma unroll
            for (int m = 0; m < 4; m++) {
                u64 w2 = w1u[(i * 4 + m) * 32 + lane];
                h2[m][0] = fma2(zd0, w2, h2[m][0]);
                h2[m][1] = fma2(zd1, w2, h2[m][1]);
                h2[m][2] = fma2(zd2, w2, h2[m][2]);
                h2[m][3] = fma2(zd3, w2, h2[m][3]);
            }
        }

#pragma unroll
        for (int m = 0; m < 4; m++) {
            float2 q0 = unpk(h2[m][0]), q1 = unpk(h2[m][1]);
            float2 q2 = unpk(h2[m][2]), q3 = unpk(h2[m][3]);
            int jlo = lane + 64 * m, jhi = jlo + 32;
            *(u64*)&hb[jlo * 4]     = pk(gelu_f(q0.x), gelu_f(q1.x));
            *(u64*)&hb[jlo * 4 + 2] = pk(gelu_f(q2.x), gelu_f(q3.x));
            *(u64*)&hb[jhi * 4]     = pk(gelu_f(q0.y), gelu_f(q1.y));
            *(u64*)&hb[jhi * 4 + 2] = pk(gelu_f(q2.y), gelu_f(q3.y));
        }
        __syncwarp();

        u64 f0a = dup2(bo0), f0b = dup2(bo0);
        u64 f1a = dup2(bo1), f1b = dup2(bo1);
#pragma unroll 4
        for (int j = 0; j < 256; j++) {
            float2 wv = unpk(w2u[j * 32 + lane]);            // 1 LDS.64
            u64 w0d = dup2(wv.x), w1d = dup2(wv.y);
            ulonglong2 hv = *(const ulonglong2*)&hb[j * 4];  // 1 LDS.128 broadcast
            f0a = fma2(hv.x, w0d, f0a); f0b = fma2(hv.y, w0d, f0b);
            f1a = fma2(hv.x, w1d, f1a); f1b = fma2(hv.y, w1d, f1b);
        }
        float2 F0a = unpk(f0a), F0b = unpk(f0b), F1a = unpk(f1a), F1b = unpk(f1b);
        float f0[4] = {F0a.x, F0a.y, F0b.x, F0b.y};
        float f1[4] = {F1a.x, F1a.y, F1b.x, F1b.y};

#pragma unroll
        for (int p = 0; p < 4; p++) {
            const int pix = base + p;
            float o0 = za[p][0] + f0[p];
            float o1 = za[p][1] + f1[p];
            if (nchw) {
                int b = pix >> 14, y = (pix >> 7) & 127, x = pix & 127;
                out[(((size_t)b * 64 + lane) * 128 + y) * 128 + x] = o0;
                out[(((size_t)b * 64 + lane + 32) * 128 + y) * 128 + x] = o1;
            } else {
                out[(size_t)pix * 64 + lane] = o0;
                out[(size_t)pix * 64 + 32 + lane] = o1;
            }
        }
#pragma unroll
        for (int p = 0; p < 4; p++) { a[p][0] = an[p][0]; a[p][1] = an[p][1]; }
        __syncwarp();
    }
}

// ---------------------------------------------------------------------------
// 1x1 fusion conv — same vectorized-LDS structure as fc2.
//  fw pre-paired (o, o+32) keyed by k; v transposed [k][4px].
// ---------------------------------------------------------------------------
#define FUSE_SMEM_FLOATS (256*64 + 64 + 8*4*256)
#define FUSE_SMEM_BYTES  (FUSE_SMEM_FLOATS * 4)

__global__ __launch_bounds__(256)
void fuse_kernel(const float* __restrict__ in0, const float* __restrict__ in1,
                 const float* __restrict__ in2, const float* __restrict__ in3,
                 const float* __restrict__ fw, const float* __restrict__ fb,
                 float* __restrict__ out, int npix)
{
    extern __shared__ __align__(16) float smf[];
    float* sFw = smf;              // 16384: pairs [k*32+lane] = (fw[lane][k], fw[lane+32][k])
    float* sfb = sFw + 16384;
    float* sV  = sfb + 64;         // 8 warps * 1024, transposed [k][4]

    const int tid = threadIdx.x;
    {
        float2* fwp = (float2*)sFw;
        for (int idx = tid; idx < 8192; idx += 256) {
            int lane = idx & 31, k = idx >> 5;
            fwp[idx] = make_float2(fw[(size_t)lane * 256 + k],
                                   fw[(size_t)(lane + 32) * 256 + k]);
        }
    }
    if (tid < 64) sfb[tid] = fb[tid];
    __syncthreads();

    const int warp = tid >> 5, lane = tid & 31;
    float* v = sV + warp * 1024;
    const u64* fwu = (const u64*)sFw;
    const float bo0 = sfb[lane], bo1 = sfb[lane + 32];
    const int task0 = (blockIdx.x * 8 + warp) * 4;
    const int tstride = gridDim.x * 8 * 4;

    for (int base = task0; base < npix; base += tstride) {
        const float* ins[4] = {in0, in1, in2, in3};
#pragma unroll
        for (int t = 0; t < 4; t++) {
            const float* src = ins[t];
            float a0 = src[(size_t)(base + 0) * 64 + lane];
            float a1 = src[(size_t)(base + 1) * 64 + lane];
            float a2 = src[(size_t)(base + 2) * 64 + lane];
            float a3 = src[(size_t)(base + 3) * 64 + lane];
            int k = 64 * t + lane;
            *(u64*)&v[k * 4]     = pk(a0, a1);
            *(u64*)&v[k * 4 + 2] = pk(a2, a3);
            float c0 = src[(size_t)(base + 0) * 64 + 32 + lane];
            float c1 = src[(size_t)(base + 1) * 64 + 32 + lane];
            float c2 = src[(size_t)(base + 2) * 64 + 32 + lane];
            float c3 = src[(size_t)(base + 3) * 64 + 32 + lane];
            int k2 = 64 * t + 32 + lane;
            *(u64*)&v[k2 * 4]     = pk(c0, c1);
            *(u64*)&v[k2 * 4 + 2] = pk(c2, c3);
        }
        __syncwarp();
        u64 z0a = dup2(bo0), z0b = dup2(bo0), z1a = dup2(bo1), z1b = dup2(bo1);
#pragma unroll 4
        for (int k = 0; k < 256; k++) {
            float2 wv = unpk(fwu[k * 32 + lane]);
            u64 w0d = dup2(wv.x), w1d = dup2(wv.y);
            ulonglong2 hv = *(const ulonglong2*)&v[k * 4];
            z0a = fma2(hv.x, w0d, z0a); z0b = fma2(hv.y, w0d, z0b);
            z1a = fma2(hv.x, w1d, z1a); z1b = fma2(hv.y, w1d, z1b);
        }
        float2 Z0a = unpk(z0a), Z0b = unpk(z0b), Z1a = unpk(z1a), Z1b = unpk(z1b);
        float z0[4] = {Z0a.x, Z0a.y, Z0b.x, Z0b.y};
        float z1[4] = {Z1a.x, Z1a.y, Z1b.x, Z1b.y};
#pragma unroll
        for (int p = 0; p < 4; p++) {
            out[(size_t)(base + p) * 64 + lane] = z0[p];
            out[(size_t)(base + p) * 64 + 32 + lane] = z1[p];
        }
        __syncwarp();
    }
}

// ---------------------------------------------------------------------------
// Launch
// ---------------------------------------------------------------------------
extern "C" void kernel_launch(void* const* d_in, const int* in_sizes, int n_in,
                              void* d_out, int out_size)
{
    const float* R      = (const float*)d_in[0];
    const float* off_w1 = (const float*)d_in[1];
    const float* off_b1 = (const float*)d_in[2];
    const float* off_w2 = (const float*)d_in[3];
    const float* off_b2 = (const float*)d_in[4];
    const float* w_ll   = (const float*)d_in[5];
    const float* b_ll   = (const float*)d_in[6];
    const float* w_lh   = (const float*)d_in[7];
    const float* b_lh   = (const float*)d_in[8];
    const float* w_hl   = (const float*)d_in[9];
    const float* b_hl   = (const float*)d_in[10];
    const float* w_hh   = (const float*)d_in[11];
    const float* b_hh   = (const float*)d_in[12];
    const float* ln_w   = (const float*)d_in[13];
    const float* ln_b   = (const float*)d_in[14];
    const float* ffn_w1 = (const float*)d_in[15];
    const float* ffn_b1 = (const float*)d_in[16];
    const float* ffn_w2 = (const float*)d_in[17];
    const float* ffn_b2 = (const float*)d_in[18];
    const float* fus_w  = (const float*)d_in[19];
    const float* fus_b  = (const float*)d_in[20];
    float* out = (float*)d_out;

    float* S = nullptr;
    cudaGetSymbolAddress((void**)&S, g_scratch);

    float* off1 = S + OFF1;
    float* off2 = S + OFF2;
    float* offp = S + OFFP;
    float* pll = S + LLo;
    float* plh = S + LHo;
    float* phl = S + HLo;
    float* phh = S + HHo;
    float* zlh = S + ZLH;
    float* zhl = S + ZHL;
    float* zhh = S + ZHH;
    float* bc0 = S + BC0;
    float* bc1 = bc0 + BANDSZ;
    float* bc2 = bc1 + BANDSZ;
    float* bc3 = bc2 + BANDSZ;
    float* fz  = S + FZ;

    cudaFuncSetAttribute((const void*)ln_ffn_kernel,
                         cudaFuncAttributeMaxDynamicSharedMemorySize, LN_SMEM_BYTES);
    cudaFuncSetAttribute((const void*)fuse_kernel,
                         cudaFuncAttributeMaxDynamicSharedMemorySize, FUSE_SMEM_BYTES);

    dim3 cblk(32, 4);

    // Offset network
    conv3x3_kernel<64, 16, true,  false><<<dim3(8, 16, 8), cblk>>>(R, off_w1, off_b1, off1, 32, HF, WF);
    conv3x3_kernel<32, 6,  false, false><<<dim3(8, 16, 4), cblk>>>(off1, off_w2, off_b2, off2, 6, HF, WF);
    pool_tanh_kernel<<<(BB * 6 * H2 * W2 + 255) / 256, 256>>>(off2, offp);

    // DWT + deform
    dwt_kernel<<<(BB * CC * H2 * W2 + 255) / 256, 256>>>(R, pll, plh, phl, phh);
    deform_kernel<<<dim3(NPIX / 256, 3), 256>>>(plh, phl, phh, offp, zlh, zhl, zhh);

    // All 4 band convs in one launch
    Band4 args;
    args.in[0] = pll;  args.in[1] = zlh;  args.in[2] = zhl;  args.in[3] = zhh;
    args.w[0] = w_ll;  args.w[1] = w_lh;  args.w[2] = w_hl;  args.w[3] = w_hh;
    args.bias[0] = b_ll; args.bias[1] = b_lh; args.bias[2] = b_hl; args.bias[3] = b_hh;
    band_conv_kernel<<<dim3(4, 8, 64), cblk>>>(args, bc0);

    // LN+FFN residual over all 4 bands (in-place)
    ln_ffn_kernel<<<148, LNF_THREADS, LN_SMEM_BYTES>>>(bc0, bc0, ln_w, ln_b,
                                                       ffn_w1, ffn_b1, ffn_w2, ffn_b2,
                                                       4 * NPIX, 0);

    // 1x1 fusion conv
    fuse_kernel<<<148, 256, FUSE_SMEM_BYTES>>>(bc0, bc1, bc2, bc3, fus_w, fus_b, fz, NPIX);

    // Final LN+FFN residual, NCHW output
    ln_ffn_kernel<<<148, LNF_THREADS, LN_SMEM_BYTES>>>(fz, out, ln_w, ln_b,
                                                       ffn_w1, ffn_b1, ffn_w2, ffn_b2,
                                                       NPIX, 1);
}